// round 7
// baseline (speedup 1.0000x reference)
#include <cuda_runtime.h>
#include <math.h>

// ---- problem dims ----
#define NB 48
#define NA 16
#define LL 768            // NB*NA
#define EMB 128
#define QKVW 384
#define MPOST 2240        // 2208 valid rows padded to 70*32

// output layout in d_out (floats): policy_flat | q_values | eo
#define OUT_POLICY 0
#define OUT_Q      24576
#define OUT_EO     25344

// ---- scratch ----
__device__ __align__(256) float g_H1[LL * 256];
__device__ __align__(256) float g_H2[LL * 128];
__device__ __align__(256) float g_eoea[1536 * 128];
__device__ __align__(256) float g_x1d[1536 * 128];
__device__ __align__(256) float g_qkvd[1536 * QKVW];
__device__ __align__(256) float g_aod[MPOST * 128];
__device__ __align__(256) float g_aopd[MPOST * 128];
__device__ __align__(256) float g_qvp[2 * MPOST];
__device__ __align__(256) float g_fO[2 * 4 * LL * 32];
__device__ __align__(256) float g_fM[2 * 4 * LL];
__device__ __align__(256) float g_fL[2 * 4 * LL];

#define ACT_NONE 0
#define ACT_LEAKY 1
#define ACT_GELU 2
#define ACT_RELU 3

__device__ __forceinline__ int res_map(int m) {
    if (m < 768) return m;
    int t = m - 768;
    if (t >= 1440) return 0;
    int k = t / 96 + 1;
    int r = t % 96;
    int b = r >> 1, c = r & 1;
    int j = c ? (k - 1) : k;
    return 768 + b * 16 + j;
}

// ============================================================================
// gemm32: 32x64xK, 256 thr, 2m x 4n micro, double-buffered + depth-2
// software-pipelined smem operand reads.
// ============================================================================
template <int ACTI, bool SPLIT, bool RESG, bool COMBINE, bool QHEAD>
__global__ void __launch_bounds__(256)
gemm32(const float* __restrict__ A,
       const float* __restrict__ W, const float* __restrict__ W2,
       const float* __restrict__ bias, const float* __restrict__ bias2,
       const float* __restrict__ Res,
       const float* __restrict__ fO, const float* __restrict__ fM,
       const float* __restrict__ fL,
       const float* __restrict__ qwv, float* __restrict__ qvp,
       float* __restrict__ C, float* __restrict__ C2, float* __restrict__ C3,
       int M, int N, int K)
{
    __shared__ __align__(16) float As[2][16][34];
    __shared__ __align__(16) float Ws[2][16][64];
    __shared__ float W1s[32][4], W2s[32][4];

    const int tid = threadIdx.x;
    const int tx = tid & 15, ty = tid >> 4;
    const int m0 = blockIdx.y * 32, n0 = blockIdx.x * 64;
    const int ar = tid >> 2;
    const int ac = (tid & 3) * 4;

    const bool comb = COMBINE && (m0 < 768);
    if (COMBINE) {
        if (comb && tid < 128) {
            const int r = tid >> 2, h = tid & 3;
            const int i1 = h * LL + (m0 + r);
            const int i2 = (4 + h) * LL + (m0 + r);
            const float m1 = fM[i1], m2 = fM[i2];
            const float Mx = fmaxf(m1, m2);
            const float w1 = __expf(m1 - Mx), w2 = __expf(m2 - Mx);
            const float inv = 1.0f / (w1 * fL[i1] + w2 * fL[i2]);
            W1s[r][h] = w1 * inv;
            W2s[r][h] = w2 * inv;
        }
        __syncthreads();
    }

    auto loadA = [&](int k0) -> float4 {
        if (COMBINE && comb) {
            const int kc = k0 + ac;
            const int h = kc >> 5, d = kc & 31;
            const int l = m0 + ar;
            const float4 o1 = *(const float4*)(fO + ((size_t)h * LL + l) * 32 + d);
            const float4 o2 = *(const float4*)(fO + ((size_t)(4 + h) * LL + l) * 32 + d);
            const float w1 = W1s[ar][h], w2 = W2s[ar][h];
            return make_float4(w1 * o1.x + w2 * o2.x, w1 * o1.y + w2 * o2.y,
                               w1 * o1.z + w2 * o2.z, w1 * o1.w + w2 * o2.w);
        }
        return *(const float4*)(A + (size_t)(m0 + ar) * K + k0 + ac);
    };
    auto loadW = [&](int k0) -> float4 {
        const int n = n0 + ar;
        if (SPLIT) {
            const float* p = (n < 256) ? (W  + (size_t)n * K + k0 + ac)
                                       : (W2 + (size_t)(n - 256) * K + k0 + ac);
            return *(const float4*)p;
        }
        return *(const float4*)(W + (size_t)n * K + k0 + ac);
    };

    float acc[2][4];
#pragma unroll
    for (int i = 0; i < 2; i++)
#pragma unroll
        for (int j = 0; j < 4; j++) acc[i][j] = 0.f;

    float4 a_pre, w_pre;
    if (tid < 128) a_pre = loadA(0);
    w_pre = loadW(0);
    if (tid < 128) {
        As[0][ac + 0][ar] = a_pre.x; As[0][ac + 1][ar] = a_pre.y;
        As[0][ac + 2][ar] = a_pre.z; As[0][ac + 3][ar] = a_pre.w;
    }
    Ws[0][ac + 0][ar] = w_pre.x; Ws[0][ac + 1][ar] = w_pre.y;
    Ws[0][ac + 2][ar] = w_pre.z; Ws[0][ac + 3][ar] = w_pre.w;
    __syncthreads();

    int buf = 0;
    for (int k0 = 0; k0 < K; k0 += 16) {
        const bool has_next = (k0 + 16 < K);
        if (has_next) {
            if (tid < 128) a_pre = loadA(k0 + 16);
            w_pre = loadW(k0 + 16);
        }
        // depth-2 pipelined smem reads
        float2 a_c = *(const float2*)&As[buf][0][ty * 2];
        float4 b_c = *(const float4*)&Ws[buf][0][tx * 4];
        float2 a_n = *(const float2*)&As[buf][1][ty * 2];
        float4 b_n = *(const float4*)&Ws[buf][1][tx * 4];
#pragma unroll
        for (int kk = 0; kk < 16; kk++) {
            const float2 a = a_c;
            const float4 b = b_c;
            a_c = a_n; b_c = b_n;
            if (kk + 2 < 16) {
                a_n = *(const float2*)&As[buf][kk + 2][ty * 2];
                b_n = *(const float4*)&Ws[buf][kk + 2][tx * 4];
            }
            acc[0][0] += a.x * b.x; acc[0][1] += a.x * b.y;
            acc[0][2] += a.x * b.z; acc[0][3] += a.x * b.w;
            acc[1][0] += a.y * b.x; acc[1][1] += a.y * b.y;
            acc[1][2] += a.y * b.z; acc[1][3] += a.y * b.w;
        }
        if (has_next) {
            const int nb = buf ^ 1;
            if (tid < 128) {
                As[nb][ac + 0][ar] = a_pre.x; As[nb][ac + 1][ar] = a_pre.y;
                As[nb][ac + 2][ar] = a_pre.z; As[nb][ac + 3][ar] = a_pre.w;
            }
            Ws[nb][ac + 0][ar] = w_pre.x; Ws[nb][ac + 1][ar] = w_pre.y;
            Ws[nb][ac + 2][ar] = w_pre.z; Ws[nb][ac + 3][ar] = w_pre.w;
            __syncthreads();
            buf = nb;
        }
    }

    float qp[2] = {0.f, 0.f};
#pragma unroll
    for (int i = 0; i < 2; i++) {
        const int m = m0 + ty * 2 + i;
        const float* rres = nullptr;
        if (RESG) rres = Res + (size_t)res_map(m) * 128;
#pragma unroll
        for (int j = 0; j < 4; j++) {
            const int n = n0 + tx * 4 + j;
            if (SPLIT) {
                if (n < 256) {
                    float v = acc[i][j] + bias[n];
                    v = (v > 0.f) ? v : 0.01f * v;
                    C[(size_t)m * 256 + n] = v;
                } else {
                    float v = acc[i][j] + bias2[n - 256];
                    C2[(size_t)m * 128 + (n - 256)] = v;
                    C3[(size_t)m * 128 + (n - 256)] = v;
                }
            } else {
                float v = acc[i][j] + bias[n];
                if (RESG) v += rres[n];
                if (ACTI == ACT_LEAKY) v = (v > 0.f) ? v : 0.01f * v;
                else if (ACTI == ACT_GELU) v = 0.5f * v * (1.0f + erff(v * 0.70710678118654752f));
                else if (ACTI == ACT_RELU) v = fmaxf(v, 0.f);
                if (QHEAD) qp[i] += v * qwv[n];
                else       C[(size_t)m * N + n] = v;
            }
        }
    }
    if (QHEAD) {
#pragma unroll
        for (int i = 0; i < 2; i++) {
            float s = qp[i];
#pragma unroll
            for (int off = 8; off; off >>= 1) s += __shfl_xor_sync(0xffffffffu, s, off);
            const int m = m0 + ty * 2 + i;
            if (tx == 0 && m < 2208) qvp[blockIdx.x * MPOST + m] = s;
        }
    }
}

// ============================================================================
// gemm64: 64x64x16, 4x4 micro, double-buffered + depth-2 pipelined smem reads
// ============================================================================
__global__ void __launch_bounds__(256)
gemm64(const float* __restrict__ A, const float* __restrict__ W,
       const float* __restrict__ bias, float* __restrict__ C,
       int M, int N, int K)
{
    __shared__ __align__(16) float As[2][16][64];
    __shared__ __align__(16) float Ws[2][16][64];

    const int tid = threadIdx.x;
    const int tx = tid & 15, ty = tid >> 4;
    const int m0 = blockIdx.y * 64, n0 = blockIdx.x * 64;
    const int lr = tid >> 2, lc = (tid & 3) * 4;

    float acc[4][4];
#pragma unroll
    for (int i = 0; i < 4; i++)
#pragma unroll
        for (int j = 0; j < 4; j++) acc[i][j] = 0.f;

    float4 a_pre = *(const float4*)(A + (size_t)(m0 + lr) * K + lc);
    float4 w_pre = *(const float4*)(W + (size_t)(n0 + lr) * K + lc);
    As[0][lc + 0][lr] = a_pre.x; As[0][lc + 1][lr] = a_pre.y;
    As[0][lc + 2][lr] = a_pre.z; As[0][lc + 3][lr] = a_pre.w;
    Ws[0][lc + 0][lr] = w_pre.x; Ws[0][lc + 1][lr] = w_pre.y;
    Ws[0][lc + 2][lr] = w_pre.z; Ws[0][lc + 3][lr] = w_pre.w;
    __syncthreads();

    int buf = 0;
    for (int k0 = 0; k0 < K; k0 += 16) {
        const bool has_next = (k0 + 16 < K);
        if (has_next) {
            a_pre = *(const float4*)(A + (size_t)(m0 + lr) * K + k0 + 16 + lc);
            w_pre = *(const float4*)(W + (size_t)(n0 + lr) * K + k0 + 16 + lc);
        }
        float4 a_c = *(const float4*)&As[buf][0][ty * 4];
        float4 b_c = *(const float4*)&Ws[buf][0][tx * 4];
        float4 a_n = *(const float4*)&As[buf][1][ty * 4];
        float4 b_n = *(const float4*)&Ws[buf][1][tx * 4];
#pragma unroll
        for (int kk = 0; kk < 16; kk++) {
            const float4 a = a_c;
            const float4 b = b_c;
            a_c = a_n; b_c = b_n;
            if (kk + 2 < 16) {
                a_n = *(const float4*)&As[buf][kk + 2][ty * 4];
                b_n = *(const float4*)&Ws[buf][kk + 2][tx * 4];
            }
            acc[0][0] += a.x * b.x; acc[0][1] += a.x * b.y; acc[0][2] += a.x * b.z; acc[0][3] += a.x * b.w;
            acc[1][0] += a.y * b.x; acc[1][1] += a.y * b.y; acc[1][2] += a.y * b.z; acc[1][3] += a.y * b.w;
            acc[2][0] += a.z * b.x; acc[2][1] += a.z * b.y; acc[2][2] += a.z * b.z; acc[2][3] += a.z * b.w;
            acc[3][0] += a.w * b.x; acc[3][1] += a.w * b.y; acc[3][2] += a.w * b.z; acc[3][3] += a.w * b.w;
        }
        if (has_next) {
            const int nb = buf ^ 1;
            As[nb][lc + 0][lr] = a_pre.x; As[nb][lc + 1][lr] = a_pre.y;
            As[nb][lc + 2][lr] = a_pre.z; As[nb][lc + 3][lr] = a_pre.w;
            Ws[nb][lc + 0][lr] = w_pre.x; Ws[nb][lc + 1][lr] = w_pre.y;
            Ws[nb][lc + 2][lr] = w_pre.z; Ws[nb][lc + 3][lr] = w_pre.w;
            __syncthreads();
            buf = nb;
        }
    }

#pragma unroll
    for (int i = 0; i < 4; i++) {
        const int m = m0 + ty * 4 + i;
#pragma unroll
        for (int j = 0; j < 4; j++) {
            const int n = n0 + tx * 4 + j;
            C[(size_t)m * N + n] = acc[i][j] + bias[n];
        }
    }
}

// ============================================================================
// fused policy + ea (pipelined inner loops)
// ============================================================================
__global__ void __launch_bounds__(256)
fused_pol_ea(const float* __restrict__ H2,
             const float* __restrict__ aw3, const float* __restrict__ ab3,
             const float* __restrict__ obs,
             const float* __restrict__ eaw, const float* __restrict__ eab,
             float* __restrict__ out_policy, float* __restrict__ ea768)
{
    __shared__ __align__(16) float As[2][16][34];
    __shared__ __align__(16) float Ws[2][16][64];
    __shared__ __align__(16) float Pol[32][36];

    const int tid = threadIdx.x;
    const int tx = tid & 15, ty = tid >> 4;
    const int m0 = blockIdx.y * 32, n0 = blockIdx.x * 64;
    const int ar = tid >> 2, ac = (tid & 3) * 4;

    // ---- pass 1: policy ----
    {
        float acc[2][4];
#pragma unroll
        for (int i = 0; i < 2; i++)
#pragma unroll
            for (int j = 0; j < 4; j++) acc[i][j] = 0.f;

        auto ldA = [&](int k0) {
            return *(const float4*)(H2 + (size_t)(m0 + ar) * 128 + k0 + ac);
        };
        auto ldW = [&](int k0) {
            if (ar < 32) return *(const float4*)(aw3 + (size_t)ar * 128 + k0 + ac);
            return make_float4(0.f, 0.f, 0.f, 0.f);
        };

        float4 a_pre, w_pre;
        if (tid < 128) a_pre = ldA(0);
        w_pre = ldW(0);
        if (tid < 128) {
            As[0][ac + 0][ar] = a_pre.x; As[0][ac + 1][ar] = a_pre.y;
            As[0][ac + 2][ar] = a_pre.z; As[0][ac + 3][ar] = a_pre.w;
        }
        Ws[0][ac + 0][ar] = w_pre.x; Ws[0][ac + 1][ar] = w_pre.y;
        Ws[0][ac + 2][ar] = w_pre.z; Ws[0][ac + 3][ar] = w_pre.w;
        __syncthreads();

        int buf = 0;
        for (int k0 = 0; k0 < 128; k0 += 16) {
            const bool has_next = (k0 + 16 < 128);
            if (has_next) {
                if (tid < 128) a_pre = ldA(k0 + 16);
                w_pre = ldW(k0 + 16);
            }
            float2 a_c = *(const float2*)&As[buf][0][ty * 2];
            float4 b_c = *(const float4*)&Ws[buf][0][tx * 4];
            float2 a_n = *(const float2*)&As[buf][1][ty * 2];
            float4 b_n = *(const float4*)&Ws[buf][1][tx * 4];
#pragma unroll
            for (int kk = 0; kk < 16; kk++) {
                const float2 a = a_c;
                const float4 b = b_c;
                a_c = a_n; b_c = b_n;
                if (kk + 2 < 16) {
                    a_n = *(const float2*)&As[buf][kk + 2][ty * 2];
                    b_n = *(const float4*)&Ws[buf][kk + 2][tx * 4];
                }
                acc[0][0] += a.x * b.x; acc[0][1] += a.x * b.y;
                acc[0][2] += a.x * b.z; acc[0][3] += a.x * b.w;
                acc[1][0] += a.y * b.x; acc[1][1] += a.y * b.y;
                acc[1][2] += a.y * b.z; acc[1][3] += a.y * b.w;
            }
            if (has_next) {
                const int nb = buf ^ 1;
                if (tid < 128) {
                    As[nb][ac + 0][ar] = a_pre.x; As[nb][ac + 1][ar] = a_pre.y;
                    As[nb][ac + 2][ar] = a_pre.z; As[nb][ac + 3][ar] = a_pre.w;
                }
                Ws[nb][ac + 0][ar] = w_pre.x; Ws[nb][ac + 1][ar] = w_pre.y;
                Ws[nb][ac + 2][ar] = w_pre.z; Ws[nb][ac + 3][ar] = w_pre.w;
                __syncthreads();
                buf = nb;
            }
        }

        if (tx < 8) {
#pragma unroll
            for (int i = 0; i < 2; i++) {
                const int r = ty * 2 + i;
#pragma unroll
                for (int j = 0; j < 4; j++) {
                    const int n = tx * 4 + j;
                    float v = acc[i][j] + ab3[n];
                    v = 0.5f * v * (1.0f + erff(v * 0.70710678118654752f));
                    Pol[r][n] = v;
                    if (blockIdx.x == 0) out_policy[(size_t)(m0 + r) * 32 + n] = v;
                }
            }
        }
    }
    __syncthreads();

    // ---- pass 2: ea ----
    {
        float acc[2][4];
#pragma unroll
        for (int i = 0; i < 2; i++)
#pragma unroll
            for (int j = 0; j < 4; j++) acc[i][j] = 0.f;

        auto ldA = [&](int k0) {
            const int kc = k0 + ac;
            if (kc < 128)
                return *(const float4*)(obs + (size_t)(m0 + ar) * 128 + kc);
            return *(const float4*)&Pol[ar][kc - 128];
        };
        auto ldW = [&](int k0) {
            return *(const float4*)(eaw + (size_t)(n0 + ar) * 160 + k0 + ac);
        };

        float4 a_pre, w_pre;
        if (tid < 128) a_pre = ldA(0);
        w_pre = ldW(0);
        if (tid < 128) {
            As[0][ac + 0][ar] = a_pre.x; As[0][ac + 1][ar] = a_pre.y;
            As[0][ac + 2][ar] = a_pre.z; As[0][ac + 3][ar] = a_pre.w;
        }
        Ws[0][ac + 0][ar] = w_pre.x; Ws[0][ac + 1][ar] = w_pre.y;
        Ws[0][ac + 2][ar] = w_pre.z; Ws[0][ac + 3][ar] = w_pre.w;
        __syncthreads();

        int buf = 0;
        for (int k0 = 0; k0 < 160; k0 += 16) {
            const bool has_next = (k0 + 16 < 160);
            if (has_next) {
                if (tid < 128) a_pre = ldA(k0 + 16);
                w_pre = ldW(k0 + 16);
            }
            float2 a_c = *(const float2*)&As[buf][0][ty * 2];
            float4 b_c = *(const float4*)&Ws[buf][0][tx * 4];
            float2 a_n = *(const float2*)&As[buf][1][ty * 2];
            float4 b_n = *(const float4*)&Ws[buf][1][tx * 4];
#pragma unroll
            for (int kk = 0; kk < 16; kk++) {
                const float2 a = a_c;
                const float4 b = b_c;
                a_c = a_n; b_c = b_n;
                if (kk + 2 < 16) {
                    a_n = *(const float2*)&As[buf][kk + 2][ty * 2];
                    b_n = *(const float4*)&Ws[buf][kk + 2][tx * 4];
                }
                acc[0][0] += a.x * b.x; acc[0][1] += a.x * b.y;
                acc[0][2] += a.x * b.z; acc[0][3] += a.x * b.w;
                acc[1][0] += a.y * b.x; acc[1][1] += a.y * b.y;
                acc[1][2] += a.y * b.z; acc[1][3] += a.y * b.w;
            }
            if (has_next) {
                const int nb = buf ^ 1;
                if (tid < 128) {
                    As[nb][ac + 0][ar] = a_pre.x; As[nb][ac + 1][ar] = a_pre.y;
                    As[nb][ac + 2][ar] = a_pre.z; As[nb][ac + 3][ar] = a_pre.w;
                }
                Ws[nb][ac + 0][ar] = w_pre.x; Ws[nb][ac + 1][ar] = w_pre.y;
                Ws[nb][ac + 2][ar] = w_pre.z; Ws[nb][ac + 3][ar] = w_pre.w;
                __syncthreads();
                buf = nb;
            }
        }

#pragma unroll
        for (int i = 0; i < 2; i++) {
            const int m = m0 + ty * 2 + i;
#pragma unroll
            for (int j = 0; j < 4; j++) {
                const int n = n0 + tx * 4 + j;
                ea768[(size_t)m * 128 + n] = acc[i][j] + eab[n];
            }
        }
    }
}

// ============================================================================
// combined attention (pipelined phases A and C)
// ============================================================================
struct Flash64Smem {
    float Qs[32][68];
    float Ks[32][68];
    float Vs[64][36];
    float Ss[64][68];
    float Pt[64][68];
    float Ms[64], Ls[64], Cs[64];
};
struct ClsSmem {
    float Qc[96][36];
    float Kc[96][36];
    float Vc[96][36];
    float Sc[96][97];
};
union AttnSmem { Flash64Smem f; ClsSmem c; };

__global__ void __launch_bounds__(256)
attn_combined(const float* __restrict__ qkvd, float* __restrict__ aod,
              float* __restrict__ fO, float* __restrict__ fM, float* __restrict__ fL)
{
    extern __shared__ char raw[];
    const int bx = blockIdx.x;
    const int tid = threadIdx.x;

    if (bx < 96) {
        Flash64Smem& sm = reinterpret_cast<AttnSmem*>(raw)->f;
        const int half = bx / 48;
        const int rem = bx % 48;
        const int h = rem / 12;
        const int l0 = (rem % 12) * 64;
        const float* Qb = qkvd + h * 32;
        const float* Kb = qkvd + 128 + h * 32;
        const float* Vb = qkvd + 256 + h * 32;

#pragma unroll
        for (int t = 0; t < 2; t++) {
            const int f = tid + t * 256;
            const int r = f >> 3, c = (f & 7) * 4;
            float4 v = *(const float4*)(Qb + (size_t)(l0 + r) * QKVW + c);
            sm.Qs[c + 0][r] = v.x; sm.Qs[c + 1][r] = v.y;
            sm.Qs[c + 2][r] = v.z; sm.Qs[c + 3][r] = v.w;
        }
        if (tid < 64) { sm.Ms[tid] = -1e30f; sm.Ls[tid] = 0.f; }

        float O[2][4];
#pragma unroll
        for (int i = 0; i < 2; i++)
#pragma unroll
            for (int j = 0; j < 4; j++) O[i][j] = 0.f;

        const int txA = tid & 15, tyA = tid >> 4;
        const int rB = tid >> 2,  hB = tid & 3;
        const int txC = tid & 7,  tyC = tid >> 3;

        const int mbeg = half * 384;
        for (int m0 = mbeg; m0 < mbeg + 384; m0 += 64) {
            __syncthreads();
#pragma unroll
            for (int t = 0; t < 2; t++) {
                const int f = tid + t * 256;
                const int r = f >> 3, c = (f & 7) * 4;
                float4 kv = *(const float4*)(Kb + (size_t)(m0 + r) * QKVW + c);
                sm.Ks[c + 0][r] = kv.x; sm.Ks[c + 1][r] = kv.y;
                sm.Ks[c + 2][r] = kv.z; sm.Ks[c + 3][r] = kv.w;
                float4 vv = *(const float4*)(Vb + (size_t)(m0 + r) * QKVW + c);
                *(float4*)&sm.Vs[r][c] = vv;
            }
            __syncthreads();

            // phase A: S = Q.K^T * scale (depth-2 pipelined)
            float fa[4][4];
#pragma unroll
            for (int i = 0; i < 4; i++)
#pragma unroll
                for (int j = 0; j < 4; j++) fa[i][j] = 0.f;
            {
                float4 a_c = *(const float4*)&sm.Qs[0][tyA * 4];
                float4 b_c = *(const float4*)&sm.Ks[0][txA * 4];
                float4 a_n = *(const float4*)&sm.Qs[1][tyA * 4];
                float4 b_n = *(const float4*)&sm.Ks[1][txA * 4];
#pragma unroll
                for (int d = 0; d < 32; d++) {
                    const float4 a = a_c;
                    const float4 b = b_c;
                    a_c = a_n; b_c = b_n;
                    if (d + 2 < 32) {
                        a_n = *(const float4*)&sm.Qs[d + 2][tyA * 4];
                        b_n = *(const float4*)&sm.Ks[d + 2][txA * 4];
                    }
                    fa[0][0] += a.x * b.x; fa[0][1] += a.x * b.y; fa[0][2] += a.x * b.z; fa[0][3] += a.x * b.w;
                    fa[1][0] += a.y * b.x; fa[1][1] += a.y * b.y; fa[1][2] += a.y * b.z; fa[1][3] += a.y * b.w;
                    fa[2][0] += a.z * b.x; fa[2][1] += a.z * b.y; fa[2][2] += a.z * b.z; fa[2][3] += a.z * b.w;
                    fa[3][0] += a.w * b.x; fa[3][1] += a.w * b.y; fa[3][2] += a.w * b.z; fa[3][3] += a.w * b.w;
                }
            }
            const float sc = 0.17677669529663687f;
#pragma unroll
            for (int i = 0; i < 4; i++)
#pragma unroll
                for (int j = 0; j < 4; j++)
                    sm.Ss[tyA * 4 + i][txA * 4 + j] = fa[i][j] * sc;
            __syncthreads();

            // phase B: online softmax
            {
                const float* srow = &sm.Ss[rB][hB * 16];
                float mloc = -1e30f;
#pragma unroll
                for (int j = 0; j < 16; j++) mloc = fmaxf(mloc, srow[j]);
                mloc = fmaxf(mloc, __shfl_xor_sync(0xffffffffu, mloc, 1));
                mloc = fmaxf(mloc, __shfl_xor_sync(0xffffffffu, mloc, 2));
                float m_old = sm.Ms[rB];
                float m_new = fmaxf(m_old, mloc);
                float corr = __expf(m_old - m_new);
                float s = 0.f;
#pragma unroll
                for (int j = 0; j < 16; j++) {
                    float e = __expf(srow[j] - m_new);
                    sm.Pt[hB * 16 + j][rB] = e;
                    s += e;
                }
                s += __shfl_xor_sync(0xffffffffu, s, 1);
                s += __shfl_xor_sync(0xffffffffu, s, 2);
                if (hB == 0) {
                    sm.Ms[rB] = m_new;
                    sm.Ls[rB] = sm.Ls[rB] * corr + s;
                    sm.Cs[rB] = corr;
                }
            }
            __syncthreads();

            // phase C: O = O*corr + P.V (depth-2 pipelined, float2 P-pair)
            const float c0 = sm.Cs[tyC * 2];
            const float c1 = sm.Cs[tyC * 2 + 1];
#pragma unroll
            for (int j = 0; j < 4; j++) { O[0][j] *= c0; O[1][j] *= c1; }
            {
                float2 p_c = *(const float2*)&sm.Pt[0][tyC * 2];
                float4 v_c = *(const float4*)&sm.Vs[0][txC * 4];
                float2 p_n = *(const float2*)&sm.Pt[1][tyC * 2];
                float4 v_n = *(const float4*)&sm.Vs[1][txC * 4];
#pragma unroll
                for (int mm = 0; mm < 64; mm++) {
                    const float2 p = p_c;
                    const float4 b = v_c;
                    p_c = p_n; v_c = v_n;
                    if (mm + 2 < 64) {
                        p_n = *(const float2*)&sm.Pt[mm + 2][tyC * 2];
                        v_n = *(const float4*)&sm.Vs[mm + 2][txC * 4];
                    }
                    O[0][0] += p.x * b.x; O[0][1] += p.x * b.y; O[0][2] += p.x * b.z; O[0][3] += p.x * b.w;
                    O[1][0] += p.y * b.x; O[1][1] += p.y * b.y; O[1][2] += p.y * b.z; O[1][3] += p.y * b.w;
                }
            }
        }

        const int pb = half * 4 + h;
#pragma unroll
        for (int i = 0; i < 2; i++) {
            const int r = tyC * 2 + i;
            const int l = l0 + r;
            *(float4*)(fO + ((size_t)pb * LL + l) * 32 + txC * 4) = *(float4*)&O[i][0];
            if (txC == 0) {
                fM[(size_t)pb * LL + l] = sm.Ms[r];
                fL[(size_t)pb * LL + l] = sm.Ls[r];
            }
        }
    } else {
        ClsSmem& sm = reinterpret_cast<AttnSmem*>(raw)->c;
        const int idx = bx - 96;
        const int k = idx % 15 + 1;
        const int h = idx / 15;

#pragma unroll
        for (int t = 0; t < 3; t++) {
            const int f = tid + t * 256;
            const int r = f >> 3, c = (f & 7) * 4;
            const int b = r >> 1, cc = r & 1;
            const int j = cc ? (k - 1) : k;
            const float* base = qkvd + (size_t)(768 + b * 16 + j) * QKVW + h * 32 + c;
            *(float4*)&sm.Qc[r][c] = *(const float4*)(base);
            *(float4*)&sm.Kc[r][c] = *(const float4*)(base + 128);
            *(float4*)&sm.Vc[r][c] = *(const float4*)(base + 256);
        }
        __syncthreads();

        const int tx = tid & 15, ty = tid >> 4;
        {
            float acc[6][6];
#pragma unroll
            for (int i = 0; i < 6; i++)
#pragma unroll
                for (int j = 0; j < 6; j++) acc[i][j] = 0.f;
#pragma unroll 8
            for (int d = 0; d < 32; d++) {
                float a[6], b[6];
#pragma unroll
                for (int i = 0; i < 6; i++) a[i] = sm.Qc[ty * 6 + i][d];
#pragma unroll
                for (int j = 0; j < 6; j++) b[j] = sm.Kc[tx * 6 + j][d];
#pragma unroll
                for (int i = 0; i < 6; i++)
#pragma unroll
                    for (int j = 0; j < 6; j++) acc[i][j] += a[i] * b[j];
            }
            const float scl = 0.17677669529663687f;
#pragma unroll
            for (int i = 0; i < 6; i++)
#pragma unroll
                for (int j = 0; j < 6; j++)
                    sm.Sc[ty * 6 + i][tx * 6 + j] = acc[i][j] * scl;
        }
        __syncthreads();

        if (tid < 96) {
            float mx = -1e30f;
#pragma unroll 8
            for (int m = 0; m < 96; m++) mx = fmaxf(mx, sm.Sc[tid][m]);
            const float w0 = (float)k, w1 = (float)(16 - k);
            float s = 0.f;
#pragma unroll 8
            for (int m = 0; m < 96; m++) {
                float w = (m & 1) ? w1 : w0;
                float e = w * __expf(sm.Sc[tid][m] - mx);
                sm.Sc[tid][m] = e;
                s += e;
            }
            const float inv = 1.0f / s;
#pragma unroll 8
            for (int m = 0; m < 96; m++) sm.Sc[tid][m] *= inv;
        }
        __syncthreads();

        const int txo = tid & 7, tyo = tid >> 3;
        float o[3][4];
#pragma unroll
        for (int i = 0; i < 3; i++)
#pragma unroll
            for (int j = 0; j < 4; j++) o[i][j] = 0.f;
#pragma unroll 8
        for (int m = 0; m < 96; m++) {
            float a[3];
#pragma unroll
            for (int i = 0; i < 3; i++) a[i] = sm.Sc[tyo * 3 + i][m];
            float4 b = *(const float4*)&sm.Vc[m][txo * 4];
#pragma unroll
            for (int i = 0; i < 3; i++) {
                o[i][0] += a[i] * b.x; o[i][1] += a[i] * b.y;
                o[i][2] += a[i] * b.z; o[i][3] += a[i] * b.w;
            }
        }
#pragma unroll
        for (int i = 0; i < 3; i++) {
            const int row = 768 + (k - 1) * 96 + tyo * 3 + i;
            *(float4*)(aod + (size_t)row * 128 + h * 32 + txo * 4) = *(float4*)&o[i][0];
        }
    }
}

// ---- assemble q_values from class partials ----
__global__ void assemble(const float* __restrict__ qvp, const float* __restrict__ qb,
                         float* __restrict__ out_q)
{
    const int l = blockIdx.x * 256 + threadIdx.x;
    if (l >= 768) return;
    const int b = l >> 4, i = l & 15;
    const float qb0 = qb[0];
    float s = qvp[l] + qvp[MPOST + l] + qb0;
#pragma unroll
    for (int k = 1; k < 16; k++) {
        const int c = (i < k) ? 0 : 1;
        const int row = 768 + (k - 1) * 96 + b * 2 + c;
        s += qvp[row] + qvp[MPOST + row] + qb0;
    }
    out_q[l] = s;
}

extern "C" void kernel_launch(void* const* d_in, const int* in_sizes, int n_in,
                              void* d_out, int out_size)
{
    const float* obs = (const float*)d_in[0];
    const float* aw1 = (const float*)d_in[1];  const float* ab1 = (const float*)d_in[2];
    const float* aw2 = (const float*)d_in[3];  const float* ab2 = (const float*)d_in[4];
    const float* aw3 = (const float*)d_in[5];  const float* ab3 = (const float*)d_in[6];
    const float* eow = (const float*)d_in[7];  const float* eob = (const float*)d_in[8];
    const float* eaw = (const float*)d_in[9];  const float* eab = (const float*)d_in[10];
    const float* riw = (const float*)d_in[11]; const float* rib = (const float*)d_in[12];
    const float* roww = (const float*)d_in[13]; const float* rob = (const float*)d_in[14];
    const float* miw = (const float*)d_in[15]; const float* mib = (const float*)d_in[16];
    const float* mow = (const float*)d_in[17]; const float* mob = (const float*)d_in[18];
    const float* qw  = (const float*)d_in[19]; const float* qb  = (const float*)d_in[20];

    float* out = (float*)d_out;
    float* out_policy = out + OUT_POLICY;
    float* out_q      = out + OUT_Q;
    float* out_eo     = out + OUT_EO;

    float *H1, *H2, *eoea, *x1d, *qkvd, *aod, *aopd, *qvp, *fO, *fM, *fL;
    cudaGetSymbolAddress((void**)&H1, g_H1);
    cudaGetSymbolAddress((void**)&H2, g_H2);
    cudaGetSymbolAddress((void**)&eoea, g_eoea);
    cudaGetSymbolAddress((void**)&x1d, g_x1d);
    cudaGetSymbolAddress((void**)&qkvd, g_qkvd);
    cudaGetSymbolAddress((void**)&aod, g_aod);
    cudaGetSymbolAddress((void**)&aopd, g_aopd);
    cudaGetSymbolAddress((void**)&qvp, g_qvp);
    cudaGetSymbolAddress((void**)&fO, g_fO);
    cudaGetSymbolAddress((void**)&fM, g_fM);
    cudaGetSymbolAddress((void**)&fL, g_fL);

    cudaFuncSetAttribute(attn_combined, cudaFuncAttributeMaxDynamicSharedMemorySize,
                         (int)sizeof(AttnSmem));

    dim3 blk(256);

    gemm32<ACT_NONE, true, false, false, false><<<dim3(6, 24), blk>>>(
        obs, aw1, eow, ab1, eob, nullptr, nullptr, nullptr, nullptr, nullptr, nullptr,
        H1, out_eo, eoea, LL, 384, 128);
    gemm32<ACT_LEAKY, false, false, false, false><<<dim3(2, 24), blk>>>(
        H1, aw2, nullptr, ab2, nullptr, nullptr, nullptr, nullptr, nullptr, nullptr, nullptr,
        H2, nullptr, nullptr, LL, 128, 256);
    fused_pol_ea<<<dim3(2, 24), blk>>>(H2, aw3, ab3, obs, eaw, eab,
                                       out_policy, eoea + 768 * 128);
    gemm32<ACT_RELU, false, false, false, false><<<dim3(2, 48), blk>>>(
        eoea, riw, nullptr, rib, nullptr, nullptr, nullptr, nullptr, nullptr, nullptr, nullptr,
        x1d, nullptr, nullptr, 1536, 128, 128);
    gemm64<<<dim3(6, 24), blk>>>(x1d, miw, mib, qkvd, 1536, 384, 128);

    attn_combined<<<156, blk, sizeof(AttnSmem)>>>(qkvd, aod, fO, fM, fL);

    gemm32<ACT_NONE, false, true, true, false><<<dim3(2, 70), blk>>>(
        aod, mow, nullptr, mob, nullptr, x1d, fO, fM, fL, nullptr, nullptr,
        aopd, nullptr, nullptr, MPOST, 128, 128);
    gemm32<ACT_RELU, false, false, false, true><<<dim3(2, 70), blk>>>(
        aopd, roww, nullptr, rob, nullptr, nullptr, nullptr, nullptr, nullptr, qw, qvp,
        nullptr, nullptr, nullptr, MPOST, 128, 128);

    assemble<<<3, blk>>>(qvp, qb, out_q);

    (void)in_sizes; (void)n_in; (void)out_size;
}

// round 8
// speedup vs baseline: 1.1394x; 1.1394x over previous
#include <cuda_runtime.h>
#include <math.h>

// ---- problem dims ----
#define NB 48
#define NA 16
#define LL 768            // NB*NA
#define QKVW 384
#define MPOST 2240        // 2208 valid rows padded

// output layout in d_out (floats): policy_flat | q_values | eo
#define OUT_POLICY 0
#define OUT_Q      24576
#define OUT_EO     25344

#define ACT_NONE 0
#define ACT_LEAKY 1
#define ACT_GELU 2
#define ACT_RELU 3

// ---- scratch ----
__device__ __align__(256) float g_H1[LL * 256];
__device__ __align__(256) float g_H2p[2 * LL * 128];   // split-K partials of H2 (no bias/act)
__device__ __align__(256) float g_eaobs[LL * 128];     // obs-part of ea (+eab)
__device__ __align__(256) float g_eoea[1536 * 128];
__device__ __align__(256) float g_x1d[1536 * 128];
__device__ __align__(256) float g_qkvd[1536 * QKVW];
__device__ __align__(256) float g_aod[MPOST * 128];    // rows 768+ from cls; pads stay 0
__device__ __align__(256) float g_aopd[MPOST * 128];
__device__ __align__(256) float g_qvp[2 * MPOST];
// flash 3-way split-m partials: [q*4+h][l]
__device__ __align__(256) float g_fO[12 * LL * 32];
__device__ __align__(256) float g_fM[12 * LL];
__device__ __align__(256) float g_fL[12 * LL];

__device__ __forceinline__ int res_map(int m) {
    if (m < 768) return m;
    int t = m - 768;
    if (t >= 1440) return 0;
    int k = t / 96 + 1;
    int r = t % 96;
    int b = r >> 1, c = r & 1;
    int j = c ? (k - 1) : k;
    return 768 + b * 16 + j;
}

// ============================================================================
// smem structs
// ============================================================================
struct G32S {
    float As[2][16][34];
    float Ws[2][16][64];
    float Wc[32][4][3];      // flash combine weights [row][h][q]
};
struct G64S {
    float As[2][16][64];
    float Ws[2][16][64];
};
struct PoleaS {
    float As[2][16][34];
    float Ws[2][16][64];
    float Pol[32][36];
    float Wp[32][68];        // pol-part of eaw, [k][n]
};
struct FlashS {
    float Qs[32][68];
    float Ks[32][68];
    float Vs[64][36];
    float Ss[64][68];
    float Pt[64][68];
    float Ms[64], Ls[64], Cs[64];
};
struct ClsS {
    float Qc[96][36];
    float Kc[96][36];
    float Vc[96][36];
    float Sc[96][97];
};

// ============================================================================
// g32_body: 32x64xK tile, 256 thr, 2m x 4n micro, double-buffered (R6-proven)
// ============================================================================
template <int ACTI, bool SPLIT, bool RESG, bool COMBINE, bool QHEAD>
__device__ __forceinline__ void g32_body(
    G32S& sm, int bx, int by,
    const float* __restrict__ A, int astride,
    const float* __restrict__ W, const float* __restrict__ W2, int wstride,
    const float* __restrict__ bias, const float* __restrict__ bias2,
    const float* __restrict__ Res,
    const float* __restrict__ fO, const float* __restrict__ fM,
    const float* __restrict__ fL,
    const float* __restrict__ qwv, float* __restrict__ qvp,
    float* __restrict__ C, float* __restrict__ C2, float* __restrict__ C3,
    int m_base, int N, int K)
{
    const int tid = threadIdx.x;
    const int tx = tid & 15, ty = tid >> 4;
    const int m0 = by * 32, n0 = bx * 64;
    const int ar = tid >> 2;
    const int ac = (tid & 3) * 4;

    if (COMBINE) {
        if (tid < 128) {
            const int r = tid >> 2, h = tid & 3;
            const int l = m0 + r;
            float mv[3], Lv[3];
            float Mx = -1e30f;
#pragma unroll
            for (int q = 0; q < 3; q++) {
                mv[q] = fM[(q * 4 + h) * LL + l];
                Lv[q] = fL[(q * 4 + h) * LL + l];
                Mx = fmaxf(Mx, mv[q]);
            }
            float den = 0.f, wq[3];
#pragma unroll
            for (int q = 0; q < 3; q++) { wq[q] = __expf(mv[q] - Mx); den += wq[q] * Lv[q]; }
            const float inv = 1.0f / den;
#pragma unroll
            for (int q = 0; q < 3; q++) sm.Wc[r][h][q] = wq[q] * inv;
        }
        __syncthreads();
    }

    auto loadA = [&](int k0) -> float4 {
        if (COMBINE) {
            const int kc = k0 + ac;
            const int h = kc >> 5, d = kc & 31;
            const int l = m0 + ar;
            float4 o = make_float4(0.f, 0.f, 0.f, 0.f);
#pragma unroll
            for (int q = 0; q < 3; q++) {
                const float w = sm.Wc[ar][h][q];
                const float4 oq = *(const float4*)(fO + ((size_t)(q * 4 + h) * LL + l) * 32 + d);
                o.x += w * oq.x; o.y += w * oq.y; o.z += w * oq.z; o.w += w * oq.w;
            }
            return o;
        }
        return *(const float4*)(A + (size_t)(m0 + ar) * astride + k0 + ac);
    };
    auto loadW = [&](int k0) -> float4 {
        const int n = n0 + ar;
        if (SPLIT) {
            const float* p = (n < 256) ? (W  + (size_t)n * wstride + k0 + ac)
                                       : (W2 + (size_t)(n - 256) * wstride + k0 + ac);
            return *(const float4*)p;
        }
        return *(const float4*)(W + (size_t)n * wstride + k0 + ac);
    };

    float acc[2][4];
#pragma unroll
    for (int i = 0; i < 2; i++)
#pragma unroll
        for (int j = 0; j < 4; j++) acc[i][j] = 0.f;

    float4 a_pre, w_pre;
    if (tid < 128) a_pre = loadA(0);
    w_pre = loadW(0);
    if (tid < 128) {
        sm.As[0][ac + 0][ar] = a_pre.x; sm.As[0][ac + 1][ar] = a_pre.y;
        sm.As[0][ac + 2][ar] = a_pre.z; sm.As[0][ac + 3][ar] = a_pre.w;
    }
    sm.Ws[0][ac + 0][ar] = w_pre.x; sm.Ws[0][ac + 1][ar] = w_pre.y;
    sm.Ws[0][ac + 2][ar] = w_pre.z; sm.Ws[0][ac + 3][ar] = w_pre.w;
    __syncthreads();

    int buf = 0;
    for (int k0 = 0; k0 < K; k0 += 16) {
        const bool has_next = (k0 + 16 < K);
        if (has_next) {
            if (tid < 128) a_pre = loadA(k0 + 16);
            w_pre = loadW(k0 + 16);
        }
#pragma unroll
        for (int kk = 0; kk < 16; kk++) {
            const float2 a = *(const float2*)&sm.As[buf][kk][ty * 2];
            const float4 b = *(const float4*)&sm.Ws[buf][kk][tx * 4];
            acc[0][0] += a.x * b.x; acc[0][1] += a.x * b.y;
            acc[0][2] += a.x * b.z; acc[0][3] += a.x * b.w;
            acc[1][0] += a.y * b.x; acc[1][1] += a.y * b.y;
            acc[1][2] += a.y * b.z; acc[1][3] += a.y * b.w;
        }
        if (has_next) {
            const int nb = buf ^ 1;
            if (tid < 128) {
                sm.As[nb][ac + 0][ar] = a_pre.x; sm.As[nb][ac + 1][ar] = a_pre.y;
                sm.As[nb][ac + 2][ar] = a_pre.z; sm.As[nb][ac + 3][ar] = a_pre.w;
            }
            sm.Ws[nb][ac + 0][ar] = w_pre.x; sm.Ws[nb][ac + 1][ar] = w_pre.y;
            sm.Ws[nb][ac + 2][ar] = w_pre.z; sm.Ws[nb][ac + 3][ar] = w_pre.w;
            __syncthreads();
            buf = nb;
        }
    }

    float qp[2] = {0.f, 0.f};
#pragma unroll
    for (int i = 0; i < 2; i++) {
        const int m = m0 + ty * 2 + i;
        const int gm = m_base + m;
        const float* rres = nullptr;
        if (RESG) rres = Res + (size_t)res_map(gm) * 128;
#pragma unroll
        for (int j = 0; j < 4; j++) {
            const int n = n0 + tx * 4 + j;
            if (SPLIT) {
                if (n < 256) {
                    float v = acc[i][j] + bias[n];
                    v = (v > 0.f) ? v : 0.01f * v;
                    C[(size_t)m * 256 + n] = v;
                } else {
                    float v = acc[i][j] + bias2[n - 256];
                    C2[(size_t)m * 128 + (n - 256)] = v;
                    C3[(size_t)m * 128 + (n - 256)] = v;
                }
            } else {
                float v = acc[i][j];
                if (bias) v += bias[n];
                if (RESG) v += rres[n];
                if (ACTI == ACT_LEAKY) v = (v > 0.f) ? v : 0.01f * v;
                else if (ACTI == ACT_GELU) v = 0.5f * v * (1.0f + erff(v * 0.70710678118654752f));
                else if (ACTI == ACT_RELU) v = fmaxf(v, 0.f);
                if (QHEAD) qp[i] += v * qwv[n];
                else       C[(size_t)m * N + n] = v;
            }
        }
    }
    if (QHEAD) {
#pragma unroll
        for (int i = 0; i < 2; i++) {
            float s = qp[i];
#pragma unroll
            for (int off = 8; off; off >>= 1) s += __shfl_xor_sync(0xffffffffu, s, off);
            const int gm = m_base + m0 + ty * 2 + i;
            if (tx == 0 && gm < 2208) qvp[bx * MPOST + gm] = s;
        }
    }
}

// ============================================================================
// g64_body: 64x64x16 tile, 4x4 micro (R6-proven)
// ============================================================================
__device__ __forceinline__ void g64_body(
    G64S& sm, int bx, int by,
    const float* __restrict__ A, const float* __restrict__ W,
    const float* __restrict__ bias, float* __restrict__ C, int N, int K)
{
    const int tid = threadIdx.x;
    const int tx = tid & 15, ty = tid >> 4;
    const int m0 = by * 64, n0 = bx * 64;
    const int lr = tid >> 2, lc = (tid & 3) * 4;

    float acc[4][4];
#pragma unroll
    for (int i = 0; i < 4; i++)
#pragma unroll
        for (int j = 0; j < 4; j++) acc[i][j] = 0.f;

    float4 a_pre = *(const float4*)(A + (size_t)(m0 + lr) * K + lc);
    float4 w_pre = *(const float4*)(W + (size_t)(n0 + lr) * K + lc);
    sm.As[0][lc + 0][lr] = a_pre.x; sm.As[0][lc + 1][lr] = a_pre.y;
    sm.As[0][lc + 2][lr] = a_pre.z; sm.As[0][lc + 3][lr] = a_pre.w;
    sm.Ws[0][lc + 0][lr] = w_pre.x; sm.Ws[0][lc + 1][lr] = w_pre.y;
    sm.Ws[0][lc + 2][lr] = w_pre.z; sm.Ws[0][lc + 3][lr] = w_pre.w;
    __syncthreads();

    int buf = 0;
    for (int k0 = 0; k0 < K; k0 += 16) {
        const bool has_next = (k0 + 16 < K);
        if (has_next) {
            a_pre = *(const float4*)(A + (size_t)(m0 + lr) * K + k0 + 16 + lc);
            w_pre = *(const float4*)(W + (size_t)(n0 + lr) * K + k0 + 16 + lc);
        }
#pragma unroll
        for (int kk = 0; kk < 16; kk++) {
            float4 a = *(const float4*)&sm.As[buf][kk][ty * 4];
            float4 b = *(const float4*)&sm.Ws[buf][kk][tx * 4];
            acc[0][0] += a.x * b.x; acc[0][1] += a.x * b.y; acc[0][2] += a.x * b.z; acc[0][3] += a.x * b.w;
            acc[1][0] += a.y * b.x; acc[1][1] += a.y * b.y; acc[1][2] += a.y * b.z; acc[1][3] += a.y * b.w;
            acc[2][0] += a.z * b.x; acc[2][1] += a.z * b.y; acc[2][2] += a.z * b.z; acc[2][3] += a.z * b.w;
            acc[3][0] += a.w * b.x; acc[3][1] += a.w * b.y; acc[3][2] += a.w * b.z; acc[3][3] += a.w * b.w;
        }
        if (has_next) {
            const int nb = buf ^ 1;
            sm.As[nb][lc + 0][lr] = a_pre.x; sm.As[nb][lc + 1][lr] = a_pre.y;
            sm.As[nb][lc + 2][lr] = a_pre.z; sm.As[nb][lc + 3][lr] = a_pre.w;
            sm.Ws[nb][lc + 0][lr] = w_pre.x; sm.Ws[nb][lc + 1][lr] = w_pre.y;
            sm.Ws[nb][lc + 2][lr] = w_pre.z; sm.Ws[nb][lc + 3][lr] = w_pre.w;
            __syncthreads();
            buf = nb;
        }
    }

#pragma unroll
    for (int i = 0; i < 4; i++) {
        const int m = m0 + ty * 4 + i;
#pragma unroll
        for (int j = 0; j < 4; j++) {
            const int n = n0 + tx * 4 + j;
            C[(size_t)m * N + n] = acc[i][j] + bias[n];
        }
    }
}

// ============================================================================
// polea_body: pass1 policy = gelu(leaky(H2p0+H2p1+ab2) @ aw3^T + ab3)
//             pass2 ea = policy @ eaw_pol^T + ea_obs   -> eoea rows 768+
// ============================================================================
__device__ __forceinline__ void polea_body(
    PoleaS& sm, int bx, int by,
    const float* __restrict__ H2p, const float* __restrict__ ab2,
    const float* __restrict__ aw3, const float* __restrict__ ab3,
    const float* __restrict__ eaw, const float* __restrict__ eaobs,
    float* __restrict__ out_policy, float* __restrict__ eoea)
{
    const int tid = threadIdx.x;
    const int tx = tid & 15, ty = tid >> 4;
    const int m0 = by * 32, n0 = bx * 64;
    const int ar = tid >> 2, ac = (tid & 3) * 4;

    // ---- pass 1: policy ----
    {
        float acc[2][4];
#pragma unroll
        for (int i = 0; i < 2; i++)
#pragma unroll
            for (int j = 0; j < 4; j++) acc[i][j] = 0.f;

        auto ldA = [&](int k0) -> float4 {
            const int kc = k0 + ac;
            const size_t off = (size_t)(m0 + ar) * 128 + kc;
            const float4 p0 = *(const float4*)(H2p + off);
            const float4 p1 = *(const float4*)(H2p + (size_t)LL * 128 + off);
            const float4 bb = *(const float4*)(ab2 + kc);
            float4 v;
            v.x = p0.x + p1.x + bb.x; v.x = (v.x > 0.f) ? v.x : 0.01f * v.x;
            v.y = p0.y + p1.y + bb.y; v.y = (v.y > 0.f) ? v.y : 0.01f * v.y;
            v.z = p0.z + p1.z + bb.z; v.z = (v.z > 0.f) ? v.z : 0.01f * v.z;
            v.w = p0.w + p1.w + bb.w; v.w = (v.w > 0.f) ? v.w : 0.01f * v.w;
            return v;
        };
        auto ldW = [&](int k0) -> float4 {
            if (ar < 32) return *(const float4*)(aw3 + (size_t)ar * 128 + k0 + ac);
            return make_float4(0.f, 0.f, 0.f, 0.f);
        };

        float4 a_pre, w_pre;
        if (tid < 128) a_pre = ldA(0);
        w_pre = ldW(0);
        if (tid < 128) {
            sm.As[0][ac + 0][ar] = a_pre.x; sm.As[0][ac + 1][ar] = a_pre.y;
            sm.As[0][ac + 2][ar] = a_pre.z; sm.As[0][ac + 3][ar] = a_pre.w;
        }
        sm.Ws[0][ac + 0][ar] = w_pre.x; sm.Ws[0][ac + 1][ar] = w_pre.y;
        sm.Ws[0][ac + 2][ar] = w_pre.z; sm.Ws[0][ac + 3][ar] = w_pre.w;
        __syncthreads();

        int buf = 0;
        for (int k0 = 0; k0 < 128; k0 += 16) {
            const bool has_next = (k0 + 16 < 128);
            if (has_next) {
                if (tid < 128) a_pre = ldA(k0 + 16);
                w_pre = ldW(k0 + 16);
            }
#pragma unroll
            for (int kk = 0; kk < 16; kk++) {
                const float2 a = *(const float2*)&sm.As[buf][kk][ty * 2];
                const float4 b = *(const float4*)&sm.Ws[buf][kk][tx * 4];
                acc[0][0] += a.x * b.x; acc[0][1] += a.x * b.y;
                acc[0][2] += a.x * b.z; acc[0][3] += a.x * b.w;
                acc[1][0] += a.y * b.x; acc[1][1] += a.y * b.y;
                acc[1][2] += a.y * b.z; acc[1][3] += a.y * b.w;
            }
            if (has_next) {
                const int nb = buf ^ 1;
                if (tid < 128) {
                    sm.As[nb][ac + 0][ar] = a_pre.x; sm.As[nb][ac + 1][ar] = a_pre.y;
                    sm.As[nb][ac + 2][ar] = a_pre.z; sm.As[nb][ac + 3][ar] = a_pre.w;
                }
                sm.Ws[nb][ac + 0][ar] = w_pre.x; sm.Ws[nb][ac + 1][ar] = w_pre.y;
                sm.Ws[nb][ac + 2][ar] = w_pre.z; sm.Ws[nb][ac + 3][ar] = w_pre.w;
                __syncthreads();
                buf = nb;
            }
        }

        if (tx < 8) {
#pragma unroll
            for (int i = 0; i < 2; i++) {
                const int r = ty * 2 + i;
#pragma unroll
                for (int j = 0; j < 4; j++) {
                    const int n = tx * 4 + j;
                    float v = acc[i][j] + ab3[n];
                    v = 0.5f * v * (1.0f + erff(v * 0.70710678118654752f));
                    sm.Pol[r][n] = v;
                    if (bx == 0) out_policy[(size_t)(m0 + r) * 32 + n] = v;
                }
            }
        }
    }
    __syncthreads();

    // stage eaw pol-part: Wp[k][n] = eaw[(n0+n)*160 + 128 + k]
    for (int idx = tid; idx < 2048; idx += 256) {
        const int k = idx >> 6, n = idx & 63;
        sm.Wp[k][n] = eaw[(size_t)(n0 + n) * 160 + 128 + k];
    }
    __syncthreads();

    // ---- pass 2: ea = Pol @ Wp + ea_obs ----
    {
        float acc[2][4];
#pragma unroll
        for (int i = 0; i < 2; i++)
#pragma unroll
            for (int j = 0; j < 4; j++) acc[i][j] = 0.f;

#pragma unroll
        for (int kk = 0; kk < 32; kk++) {
            const float a0 = sm.Pol[ty * 2][kk];
            const float a1 = sm.Pol[ty * 2 + 1][kk];
            const float4 b = *(const float4*)&sm.Wp[kk][tx * 4];
            acc[0][0] += a0 * b.x; acc[0][1] += a0 * b.y;
            acc[0][2] += a0 * b.z; acc[0][3] += a0 * b.w;
            acc[1][0] += a1 * b.x; acc[1][1] += a1 * b.y;
            acc[1][2] += a1 * b.z; acc[1][3] += a1 * b.w;
        }
#pragma unroll
        for (int i = 0; i < 2; i++) {
            const int m = m0 + ty * 2 + i;
#pragma unroll
            for (int j = 0; j < 4; j++) {
                const int n = n0 + tx * 4 + j;
                eoea[(size_t)(768 + m) * 128 + n] =
                    acc[i][j] + eaobs[(size_t)m * 128 + n];
            }
        }
    }
}

// ============================================================================
// flash_body: 3-way split-m (256 keys per quarter), unnormalized partials
// ============================================================================
__device__ __forceinline__ void flash_body(
    char* raw, int q, int h, int l0,
    const float* __restrict__ qkvd,
    float* __restrict__ fO, float* __restrict__ fM, float* __restrict__ fL)
{
    FlashS& sm = *reinterpret_cast<FlashS*>(raw);
    const int tid = threadIdx.x;
    const float* Qb = qkvd + h * 32;
    const float* Kb = qkvd + 128 + h * 32;
    const float* Vb = qkvd + 256 + h * 32;

#pragma unroll
    for (int t = 0; t < 2; t++) {
        const int f = tid + t * 256;
        const int r = f >> 3, c = (f & 7) * 4;
        float4 v = *(const float4*)(Qb + (size_t)(l0 + r) * QKVW + c);
        sm.Qs[c + 0][r] = v.x; sm.Qs[c + 1][r] = v.y;
        sm.Qs[c + 2][r] = v.z; sm.Qs[c + 3][r] = v.w;
    }
    if (tid < 64) { sm.Ms[tid] = -1e30f; sm.Ls[tid] = 0.f; }

    float O[2][4];
#pragma unroll
    for (int i = 0; i < 2; i++)
#pragma unroll
        for (int j = 0; j < 4; j++) O[i][j] = 0.f;

    const int txA = tid & 15, tyA = tid >> 4;
    const int rB = tid >> 2,  hB = tid & 3;
    const int txC = tid & 7,  tyC = tid >> 3;

    const int mbeg = q * 256;
    for (int m0k = mbeg; m0k < mbeg + 256; m0k += 64) {
        __syncthreads();
#pragma unroll
        for (int t = 0; t < 2; t++) {
            const int f = tid + t * 256;
            const int r = f >> 3, c = (f & 7) * 4;
            float4 kv = *(const float4*)(Kb + (size_t)(m0k + r) * QKVW + c);
            sm.Ks[c + 0][r] = kv.x; sm.Ks[c + 1][r] = kv.y;
            sm.Ks[c + 2][r] = kv.z; sm.Ks[c + 3][r] = kv.w;
            float4 vv = *(const float4*)(Vb + (size_t)(m0k + r) * QKVW + c);
            *(float4*)&sm.Vs[r][c] = vv;
        }
        __syncthreads();

        float fa[4][4];
#pragma unroll
        for (int i = 0; i < 4; i++)
#pragma unroll
            for (int j = 0; j < 4; j++) fa[i][j] = 0.f;
#pragma unroll 8
        for (int d = 0; d < 32; d++) {
            float4 a = *(const float4*)&sm.Qs[d][tyA * 4];
            float4 b = *(const float4*)&sm.Ks[d][txA * 4];
            fa[0][0] += a.x * b.x; fa[0][1] += a.x * b.y; fa[0][2] += a.x * b.z; fa[0][3] += a.x * b.w;
            fa[1][0] += a.y * b.x; fa[1][1] += a.y * b.y; fa[1][2] += a.y * b.z; fa[1][3] += a.y * b.w;
            fa[2][0] += a.z * b.x; fa[2][1] += a.z * b.y; fa[2][2] += a.z * b.z; fa[2][3] += a.z * b.w;
            fa[3][0] += a.w * b.x; fa[3][1] += a.w * b.y; fa[3][2] += a.w * b.z; fa[3][3] += a.w * b.w;
        }
        const float sc = 0.17677669529663687f;
#pragma unroll
        for (int i = 0; i < 4; i++)
#pragma unroll
            for (int j = 0; j < 4; j++)
                sm.Ss[tyA * 4 + i][txA * 4 + j] = fa[i][j] * sc;
        __syncthreads();

        {
            const float* srow = &sm.Ss[rB][hB * 16];
            float mloc = -1e30f;
#pragma unroll
            for (int j = 0; j < 16; j++) mloc = fmaxf(mloc, srow[j]);
            mloc = fmaxf(mloc, __shfl_xor_sync(0xffffffffu, mloc, 1));
            mloc = fmaxf(mloc, __shfl_xor_sync(0xffffffffu, mloc, 2));
            float m_old = sm.Ms[rB];
            float m_new = fmaxf(m_old, mloc);
            float corr = __expf(m_old - m_new);
            float s = 0.f;
#pragma unroll
            for (int j = 0; j < 16; j++) {
                float e = __expf(srow[j] - m_new);
                sm.Pt[hB * 16 + j][rB] = e;
                s += e;
            }
            s += __shfl_xor_sync(0xffffffffu, s, 1);
            s += __shfl_xor_sync(0xffffffffu, s, 2);
            if (hB == 0) {
                sm.Ms[rB] = m_new;
                sm.Ls[rB] = sm.Ls[rB] * corr + s;
                sm.Cs[rB] = corr;
            }
        }
        __syncthreads();

        const float c0 = sm.Cs[tyC * 2];
        const float c1 = sm.Cs[tyC * 2 + 1];
#pragma unroll
        for (int j = 0; j < 4; j++) { O[0][j] *= c0; O[1][j] *= c1; }
#pragma unroll 8
        for (int mm = 0; mm < 64; mm++) {
            const float a0 = sm.Pt[mm][tyC * 2];
            const float a1 = sm.Pt[mm][tyC * 2 + 1];
            float4 b = *(const float4*)&sm.Vs[mm][txC * 4];
            O[0][0] += a0 * b.x; O[0][1] += a0 * b.y; O[0][2] += a0 * b.z; O[0][3] += a0 * b.w;
            O[1][0] += a1 * b.x; O[1][1] += a1 * b.y; O[1][2] += a1 * b.z; O[1][3] += a1 * b.w;
        }
    }

    const int pb = q * 4 + h;
#pragma unroll
    for (int i = 0; i < 2; i++) {
        const int r = tyC * 2 + i;
        const int l = l0 + r;
        *(float4*)(fO + ((size_t)pb * LL + l) * 32 + txC * 4) = *(float4*)&O[i][0];
        if (txC == 0) {
            fM[(size_t)pb * LL + l] = sm.Ms[r];
            fL[(size_t)pb * LL + l] = sm.Ls[r];
        }
    }
}

// ============================================================================
// cls_body: class attention for slots k>=1 (R6-proven)
// ============================================================================
__device__ __forceinline__ void cls_body(
    char* raw, int k, int h,
    const float* __restrict__ qkvd, float* __restrict__ aod)
{
    ClsS& sm = *reinterpret_cast<ClsS*>(raw);
    const int tid = threadIdx.x;

#pragma unroll
    for (int t = 0; t < 3; t++) {
        const int f = tid + t * 256;
        const int r = f >> 3, c = (f & 7) * 4;
        const int b = r >> 1, cc = r & 1;
        const int j = cc ? (k - 1) : k;
        const float* base = qkvd + (size_t)(768 + b * 16 + j) * QKVW + h * 32 + c;
        *(float4*)&sm.Qc[r][c] = *(const float4*)(base);
        *(float4*)&sm.Kc[r][c] = *(const float4*)(base + 128);
        *(float4*)&sm.Vc[r][c] = *(const float4*)(base + 256);
    }
    __syncthreads();

    const int tx = tid & 15, ty = tid >> 4;
    {
        float acc[6][6];
#pragma unroll
        for (int i = 0; i < 6; i++)
#pragma unroll
            for (int j = 0; j < 6; j++) acc[i][j] = 0.f;
#pragma unroll 8
        for (int d = 0; d < 32; d++) {
            float a[6], b[6];
#pragma unroll
            for (int i = 0; i < 6; i++) a[i] = sm.Qc[ty * 6 + i][d];
#pragma unroll
            for (int j = 0; j < 6; j++) b[j] = sm.Kc[tx * 6 + j][d];
#pragma unroll
            for (int i = 0; i < 6; i++)
#pragma unroll
                for (int j = 0; j < 6; j++) acc[i][j] += a[i] * b[j];
        }
        const float scl = 0.17677669529663687f;
#pragma unroll
        for (int i = 0; i < 6; i++)
#pragma unroll
            for (int j = 0; j < 6; j++)
                sm.Sc[ty * 6 + i][tx * 6 + j] = acc[i][j] * scl;
    }
    __syncthreads();

    if (tid < 96) {
        float mx = -1e30f;
#pragma unroll 8
        for (int m = 0; m < 96; m++) mx = fmaxf(mx, sm.Sc[tid][m]);
        const float w0 = (float)k, w1 = (float)(16 - k);
        float s = 0.f;
#pragma unroll 8
        for (int m = 0; m < 96; m++) {
            float w = (m & 1) ? w1 : w0;
            float e = w * __expf(sm.Sc[tid][m] - mx);
            sm.Sc[tid][m] = e;
            s += e;
        }
        const float inv = 1.0f / s;
#pragma unroll 8
        for (int m = 0; m < 96; m++) sm.Sc[tid][m] *= inv;
    }
    __syncthreads();

    const int txo = tid & 7, tyo = tid >> 3;
    float o[3][4];
#pragma unroll
    for (int i = 0; i < 3; i++)
#pragma unroll
        for (int j = 0; j < 4; j++) o[i][j] = 0.f;
#pragma unroll 8
    for (int m = 0; m < 96; m++) {
        float a[3];
#pragma unroll
        for (int i = 0; i < 3; i++) a[i] = sm.Sc[tyo * 3 + i][m];
        float4 b = *(const float4*)&sm.Vc[m][txo * 4];
#pragma unroll
        for (int i = 0; i < 3; i++) {
            o[i][0] += a[i] * b.x; o[i][1] += a[i] * b.y;
            o[i][2] += a[i] * b.z; o[i][3] += a[i] * b.w;
        }
    }
#pragma unroll
    for (int i = 0; i < 3; i++) {
        const int row = 768 + (k - 1) * 96 + tyo * 3 + i;
        *(float4*)(aod + (size_t)row * 128 + h * 32 + txo * 4) = *(float4*)&o[i][0];
    }
}

// ============================================================================
// dispatch kernels (merged launches)
// ============================================================================
__global__ void __launch_bounds__(256)
k_L1(const float* obs, const float* aw1, const float* ab1,
     const float* eow, const float* eob,
     float* H1, float* out_eo, float* eoea)
{
    extern __shared__ char raw[];
    g32_body<ACT_NONE, true, false, false, false>(
        *(G32S*)raw, blockIdx.x % 6, blockIdx.x / 6,
        obs, 128, aw1, eow, 128, ab1, eob, nullptr,
        nullptr, nullptr, nullptr, nullptr, nullptr,
        H1, out_eo, eoea, 0, 384, 128);
}

__global__ void __launch_bounds__(256)
k_L2(const float* H1, const float* aw2, float* H2p,
     const float* obs, const float* eaw, const float* eab, float* eaobs)
{
    extern __shared__ char raw[];
    G32S& sm = *(G32S*)raw;
    const int b = blockIdx.x;
    if (b < 96) {   // G2 split-K partials
        const int kz = b / 48, r = b % 48;
        g32_body<ACT_NONE, false, false, false, false>(
            sm, r % 2, r / 2,
            H1 + kz * 128, 256, aw2 + kz * 128, nullptr, 256,
            nullptr, nullptr, nullptr, nullptr, nullptr, nullptr, nullptr, nullptr,
            H2p + (size_t)kz * LL * 128, nullptr, nullptr, 0, 128, 128);
    } else {        // ea_obs = obs @ eaw[:, :128]^T + eab
        const int r = b - 96;
        g32_body<ACT_NONE, false, false, false, false>(
            sm, r % 2, r / 2,
            obs, 128, eaw, nullptr, 160,
            eab, nullptr, nullptr, nullptr, nullptr, nullptr, nullptr, nullptr,
            eaobs, nullptr, nullptr, 0, 128, 128);
    }
}

__global__ void __launch_bounds__(256)
k_L3(const float* H2p, const float* ab2, const float* aw3, const float* ab3,
     const float* eaw, const float* eaobs, float* out_policy, float* eoea,
     const float* riw, const float* rib, float* x1d)
{
    extern __shared__ char raw[];
    const int b = blockIdx.x;
    if (b < 48) {   // policy + ea
        polea_body(*(PoleaS*)raw, b % 2, b / 2,
                   H2p, ab2, aw3, ab3, eaw, eaobs, out_policy, eoea);
    } else {        // x1 e-rows
        const int r = b - 48;
        g32_body<ACT_RELU, false, false, false, false>(
            *(G32S*)raw, r % 2, r / 2,
            eoea, 128, riw, nullptr, 128,
            rib, nullptr, nullptr, nullptr, nullptr, nullptr, nullptr, nullptr,
            x1d, nullptr, nullptr, 0, 128, 128);
    }
}

__global__ void __launch_bounds__(256)
k_L4(const float* eoea, const float* riw, const float* rib, float* x1d,
     const float* miw, const float* mib, float* qkvd)
{
    extern __shared__ char raw[];
    const int b = blockIdx.x;
    if (b < 48) {   // x1 a-rows
        g32_body<ACT_RELU, false, false, false, false>(
            *(G32S*)raw, b % 2, b / 2,
            eoea + 768 * 128, 128, riw, nullptr, 128,
            rib, nullptr, nullptr, nullptr, nullptr, nullptr, nullptr, nullptr,
            x1d + 768 * 128, nullptr, nullptr, 768, 128, 128);
    } else {        // qkv e-rows
        const int r = b - 48;
        g64_body(*(G64S*)raw, r % 6, r / 6, x1d, miw, mib, qkvd, 384, 128);
    }
}

__global__ void __launch_bounds__(256)
k_L5(const float* qkvd, float* fO, float* fM, float* fL,
     const float* x1d, const float* miw, const float* mib, float* qkvd_a)
{
    extern __shared__ char raw[];
    const int b = blockIdx.x;
    if (b < 144) {  // flash thirds
        const int q = b / 48, rem = b % 48;
        flash_body(raw, q, rem / 12, (rem % 12) * 64, qkvd, fO, fM, fL);
    } else {        // qkv a-rows
        const int r = b - 144;
        g64_body(*(G64S*)raw, r % 6, r / 6,
                 x1d + 768 * 128, miw, mib, qkvd_a + 768 * QKVW, 384, 128);
    }
}

__global__ void __launch_bounds__(256)
k_L6(const float* qkvd, float* aod,
     const float* fO, const float* fM, const float* fL,
     const float* x1d, const float* mow, const float* mob, float* aopd)
{
    extern __shared__ char raw[];
    const int b = blockIdx.x;
    if (b < 60) {   // class attention
        cls_body(raw, b % 15 + 1, b / 15, qkvd, aod);
    } else {        // G7 e-rows: out_proj + residual, flash partials combined in loader
        const int r = b - 60;
        g32_body<ACT_NONE, false, true, true, false>(
            *(G32S*)raw, r % 2, r / 2,
            nullptr, 128, mow, nullptr, 128,
            mob, nullptr, x1d, fO, fM, fL, nullptr, nullptr,
            aopd, nullptr, nullptr, 0, 128, 128);
    }
}

__global__ void __launch_bounds__(256)
k_L7(const float* aod, const float* x1d, const float* mow, const float* mob,
     float* aopd, const float* roww, const float* rob,
     const float* qw, float* qvp)
{
    extern __shared__ char raw[];
    const int b = blockIdx.x;
    if (b < 92) {   // G7 a-rows
        g32_body<ACT_NONE, false, true, false, false>(
            *(G32S*)raw, b % 2, b / 2,
            aod + 768 * 128, 128, mow, nullptr, 128,
            mob, nullptr, x1d, nullptr, nullptr, nullptr, nullptr, nullptr,
            aopd + 768 * 128, nullptr, nullptr, 768, 128, 128);
    } else {        // G8 e-rows (q-head fused)
        const int r = b - 92;
        g32_body<ACT_RELU, false, false, false, true>(
            *(G32S*)raw, r % 2, r / 2,
            aopd, 128, roww, nullptr, 128,
            rob, nullptr, nullptr, nullptr, nullptr, nullptr, qw, qvp,
            nullptr, nullptr, nullptr, 0, 128, 128);
    }
}

__global__ void __launch_bounds__(256)
k_L8(const float* aopd, const float* roww, const float* rob,
     const float* qw, float* qvp)
{
    extern __shared__ char raw[];
    g32_body<ACT_RELU, false, false, false, true>(
        *(G32S*)raw, blockIdx.x % 2, blockIdx.x / 2,
        aopd + 768 * 128, 128, roww, nullptr, 128,
        rob, nullptr, nullptr, nullptr, nullptr, nullptr, qw, qvp,
        nullptr, nullptr, nullptr, 768, 128, 128);
}

__global__ void k_L9(const float* __restrict__ qvp, const float* __restrict__ qb,
                     float* __restrict__ out_q)
{
    const int l = blockIdx.x * 256 + threadIdx.x;
    if (l >= 768) return;
    const int b = l >> 4, i = l & 15;
    const float qb0 = qb[0];
    float s = qvp[l] + qvp[MPOST + l] + qb0;
#pragma unroll
    for (int k = 1; k < 16; k++) {
        const int c = (i < k) ? 0 : 1;
        const int row = 768 + (k - 1) * 96 + b * 2 + c;
        s += qvp[row] + qvp[MPOST + row] + qb0;
    }
    out_q[l] = s;
}

extern "C" void kernel_launch(void* const* d_in, const int* in_sizes, int n_in,
                              void* d_out, int out_size)
{
    const float* obs = (const float*)d_in[0];
    const float* aw1 = (const float*)d_in[1];  const float* ab1 = (const float*)d_in[2];
    const float* aw2 = (const float*)d_in[3];  const float* ab2 = (const float*)d_in[4];
    const float* aw3 = (const float*)d_in[5];  const float* ab3 = (const float*)d_in[6];
    const float* eow = (const float*)d_in[7];  const float* eob = (const float*)d_in[8];
    const float* eaw = (const float*)d_in[9];  const float* eab = (const float*)d_in[10];
    const float* riw = (const float*)d_in[11]; const float* rib = (const float*)d_in[12];
    const float* roww = (const float*)d_in[13]; const float* rob = (const float*)d_in[14];
    const float* miw = (const float*)d_in[15]; const float* mib = (const float*)d_in[16];
    const float* mow = (const float*)d_in[17]; const float* mob = (const float*)d_in[18];
    const float* qw  = (const float*)d_in[19]; const float* qb  = (const float*)d_in[20];

    float* out = (float*)d_out;
    float* out_policy = out + OUT_POLICY;
    float* out_q      = out + OUT_Q;
    float* out_eo     = out + OUT_EO;

    float *H1, *H2p, *eaobs, *eoea, *x1d, *qkvd, *aod, *aopd, *qvp, *fO, *fM, *fL;
    cudaGetSymbolAddress((void**)&H1, g_H1);
    cudaGetSymbolAddress((void**)&H2p, g_H2p);
    cudaGetSymbolAddress((void**)&eaobs, g_eaobs);
    cudaGetSymbolAddress((void**)&eoea, g_eoea);
    cudaGetSymbolAddress((void**)&x1d, g_x1d);
    cudaGetSymbolAddress((void**)&qkvd, g_qkvd);
    cudaGetSymbolAddress((void**)&aod, g_aod);
    cudaGetSymbolAddress((void**)&aopd, g_aopd);
    cudaGetSymbolAddress((void**)&qvp, g_qvp);
    cudaGetSymbolAddress((void**)&fO, g_fO);
    cudaGetSymbolAddress((void**)&fM, g_fM);
    cudaGetSymbolAddress((void**)&fL, g_fL);

    const int s32 = (int)sizeof(G32S);
    const int s3  = (int)sizeof(PoleaS);
    const int s4  = (int)sizeof(G64S);
    const int s5  = (int)sizeof(FlashS);
    const int s6  = (int)sizeof(ClsS);

    cudaFuncSetAttribute(k_L5, cudaFuncAttributeMaxDynamicSharedMemorySize, s5);
    cudaFuncSetAttribute(k_L6, cudaFuncAttributeMaxDynamicSharedMemorySize, s6);

    dim3 blk(256);

    k_L1<<<144, blk, s32>>>(obs, aw1, ab1, eow, eob, H1, out_eo, eoea);
    k_L2<<<144, blk, s32>>>(H1, aw2, H2p, obs, eaw, eab, eaobs);
    k_L3<<<96,  blk, s3 >>>(H2p, ab2, aw3, ab3, eaw, eaobs, out_policy, eoea,
                            riw, rib, x1d);
    k_L4<<<120, blk, s4 >>>(eoea, riw, rib, x1d, miw, mib, qkvd);
    k_L5<<<216, blk, s5 >>>(qkvd, fO, fM, fL, x1d, miw, mib, qkvd);
    k_L6<<<108, blk, s6 >>>(qkvd, aod, fO, fM, fL, x1d, mow, mob, aopd);
    k_L7<<<140, blk, s32>>>(aod, x1d, mow, mob, aopd, roww, rob, qw, qvp);
    k_L8<<<92,  blk, s32>>>(aopd, roww, rob, qw, qvp);
    k_L9<<<3,   blk>>>(qvp, qb, out_q);

    (void)in_sizes; (void)n_in; (void)out_size;
}

// round 9
// speedup vs baseline: 1.1571x; 1.0155x over previous
#include <cuda_runtime.h>
#include <math.h>

// ---- problem dims ----
#define NB 48
#define NA 16
#define LL 768            // NB*NA
#define QKVW 384
#define MPOST 2240

// output layout in d_out (floats): policy_flat | q_values | eo
#define OUT_POLICY 0
#define OUT_Q      24576
#define OUT_EO     25344

#define ACT_NONE 0
#define ACT_LEAKY 1
#define ACT_GELU 2
#define ACT_RELU 3

// ---- scratch ----
__device__ __align__(256) float g_H1[LL * 256];
__device__ __align__(256) float g_H2p[2 * LL * 128];
__device__ __align__(256) float g_eaobs[LL * 128];
__device__ __align__(256) float g_eoea[1536 * 128];
__device__ __align__(256) float g_x1d[1536 * 128];
__device__ __align__(256) float g_qkvd[1536 * QKVW];
__device__ __align__(256) float g_aod[MPOST * 128];
__device__ __align__(256) float g_aopd[MPOST * 128];
__device__ __align__(256) float g_qvp[2 * MPOST];
__device__ __align__(256) float g_fO[12 * LL * 32];
__device__ __align__(256) float g_fM[12 * LL];
__device__ __align__(256) float g_fL[12 * LL];
__device__ int g_ctr;     // zero-initialized; self-resets each run

__device__ __forceinline__ int res_map(int m) {
    if (m < 768) return m;
    int t = m - 768;
    if (t >= 1440) return 0;
    int k = t / 96 + 1;
    int r = t % 96;
    int b = r >> 1, c = r & 1;
    int j = c ? (k - 1) : k;
    return 768 + b * 16 + j;
}

// ============================================================================
// smem structs (flat: full K=128 tiles resident, no mainloop barriers)
// ============================================================================
struct G32F {
    float Ar[32][132];     // A row-major
    float Ws[128][68];     // W k-major, stride 68
    float Wc[32][4][3];    // flash combine weights
};
struct G64F {
    float As[128][68];     // A k-major
    float Ws[128][68];
};
struct PoleaF {
    float Ar[32][132];
    float Ws[128][68];
    float Pol[32][36];
    float Wp[32][68];
};
struct FlashS {
    float Qs[32][68];
    float Ks[32][68];
    float Vs[64][36];
    float Ss[64][68];
    float Pt[64][68];
    float Ms[64], Ls[64], Cs[64];
};
struct ClsS {
    float Qc[96][36];
    float Kc[96][36];
    float Vc[96][36];
    float Sc[96][97];
};

// ============================================================================
// g32_flat: 32x64 tile, K=128 resident, barrier-free mainloop.
// ============================================================================
template <int ACTI, bool SPLIT, bool RESG, bool COMBINE, bool QHEAD>
__device__ __forceinline__ void g32_flat(
    G32F& sm, int bx, int by,
    const float* __restrict__ A, int astride,
    const float* __restrict__ W, const float* __restrict__ W2, int wstride,
    const float* __restrict__ bias, const float* __restrict__ bias2,
    const float* __restrict__ Res,
    const float* __restrict__ fO, const float* __restrict__ fM,
    const float* __restrict__ fL,
    const float* __restrict__ qwv, float* __restrict__ qvp,
    float* __restrict__ C, float* __restrict__ C2, float* __restrict__ C3,
    int m_base, int N)
{
    const int tid = threadIdx.x;
    const int tx = tid & 15, ty = tid >> 4;
    const int m0 = by * 32, n0 = bx * 64;

    if (COMBINE) {
        if (tid < 128) {
            const int r = tid >> 2, h = tid & 3;
            const int l = m0 + r;
            float mv[3], Lv[3];
            float Mx = -1e30f;
#pragma unroll
            for (int q = 0; q < 3; q++) {
                mv[q] = fM[(q * 4 + h) * LL + l];
                Lv[q] = fL[(q * 4 + h) * LL + l];
                Mx = fmaxf(Mx, mv[q]);
            }
            float den = 0.f, wq[3];
#pragma unroll
            for (int q = 0; q < 3; q++) { wq[q] = __expf(mv[q] - Mx); den += wq[q] * Lv[q]; }
            const float inv = 1.0f / den;
#pragma unroll
            for (int q = 0; q < 3; q++) sm.Wc[r][h][q] = wq[q] * inv;
        }
        __syncthreads();
    }

    // fill A (32 rows x 128 cols, row-major, coalesced)
#pragma unroll
    for (int t = 0; t < 4; t++) {
        const int f = tid + t * 256;
        const int r = f >> 5, c = (f & 31) * 4;
        float4 v;
        if (COMBINE) {
            const int h = c >> 5, d = c & 31;
            const int l = m0 + r;
            v = make_float4(0.f, 0.f, 0.f, 0.f);
#pragma unroll
            for (int q = 0; q < 3; q++) {
                const float w = sm.Wc[r][h][q];
                const float4 oq = *(const float4*)(fO + ((size_t)(q * 4 + h) * LL + l) * 32 + d);
                v.x += w * oq.x; v.y += w * oq.y; v.z += w * oq.z; v.w += w * oq.w;
            }
        } else {
            v = *(const float4*)(A + (size_t)(m0 + r) * astride + c);
        }
        *(float4*)&sm.Ar[r][c] = v;
    }
    // fill W (64 rows x 128 cols -> k-major; lane-distinct rows => conflict-free STS)
    {
        const int n = tid & 63;
        const int cb = tid >> 6;          // 0..3
#pragma unroll
        for (int t = 0; t < 8; t++) {
            const int c = (cb + 4 * t) * 4;
            const int gn = n0 + n;
            float4 v;
            if (SPLIT) {
                const float* p = (gn < 256) ? (W  + (size_t)gn * wstride + c)
                                            : (W2 + (size_t)(gn - 256) * wstride + c);
                v = *(const float4*)p;
            } else {
                v = *(const float4*)(W + (size_t)gn * wstride + c);
            }
            sm.Ws[c + 0][n] = v.x; sm.Ws[c + 1][n] = v.y;
            sm.Ws[c + 2][n] = v.z; sm.Ws[c + 3][n] = v.w;
        }
    }
    __syncthreads();

    float acc[2][4];
#pragma unroll
    for (int i = 0; i < 2; i++)
#pragma unroll
        for (int j = 0; j < 4; j++) acc[i][j] = 0.f;

    const float* a0p = &sm.Ar[ty * 2][0];
    const float* a1p = &sm.Ar[ty * 2 + 1][0];
#pragma unroll 32
    for (int kk = 0; kk < 128; kk++) {
        const float a0 = a0p[kk];
        const float a1 = a1p[kk];
        const float4 b = *(const float4*)&sm.Ws[kk][tx * 4];
        acc[0][0] += a0 * b.x; acc[0][1] += a0 * b.y;
        acc[0][2] += a0 * b.z; acc[0][3] += a0 * b.w;
        acc[1][0] += a1 * b.x; acc[1][1] += a1 * b.y;
        acc[1][2] += a1 * b.z; acc[1][3] += a1 * b.w;
    }

    float qp[2] = {0.f, 0.f};
#pragma unroll
    for (int i = 0; i < 2; i++) {
        const int m = m0 + ty * 2 + i;
        const int gm = m_base + m;
        const float* rres = nullptr;
        if (RESG) rres = Res + (size_t)res_map(gm) * 128;
#pragma unroll
        for (int j = 0; j < 4; j++) {
            const int n = n0 + tx * 4 + j;
            if (SPLIT) {
                if (n < 256) {
                    float v = acc[i][j] + bias[n];
                    v = (v > 0.f) ? v : 0.01f * v;
                    C[(size_t)m * 256 + n] = v;
                } else {
                    float v = acc[i][j] + bias2[n - 256];
                    C2[(size_t)m * 128 + (n - 256)] = v;
                    C3[(size_t)m * 128 + (n - 256)] = v;
                }
            } else {
                float v = acc[i][j];
                if (bias) v += bias[n];
                if (RESG) v += rres[n];
                if (ACTI == ACT_LEAKY) v = (v > 0.f) ? v : 0.01f * v;
                else if (ACTI == ACT_GELU) v = 0.5f * v * (1.0f + erff(v * 0.70710678118654752f));
                else if (ACTI == ACT_RELU) v = fmaxf(v, 0.f);
                if (QHEAD) qp[i] += v * qwv[n];
                else       C[(size_t)m * N + n] = v;
            }
        }
    }
    if (QHEAD) {
#pragma unroll
        for (int i = 0; i < 2; i++) {
            float s = qp[i];
#pragma unroll
            for (int off = 8; off; off >>= 1) s += __shfl_xor_sync(0xffffffffu, s, off);
            const int gm = m_base + m0 + ty * 2 + i;
            if (tx == 0 && gm < 2208) qvp[bx * MPOST + gm] = s;
        }
    }
}

// ============================================================================
// g64_flat: 64x64 tile, K=128 resident, barrier-free mainloop.
// ============================================================================
__device__ __forceinline__ void g64_flat(
    G64F& sm, int bx, int by,
    const float* __restrict__ A, const float* __restrict__ W,
    const float* __restrict__ bias, float* __restrict__ C, int N)
{
    const int tid = threadIdx.x;
    const int tx = tid & 15, ty = tid >> 4;
    const int m0 = by * 64, n0 = bx * 64;

    {
        const int r = tid & 63;
        const int cb = tid >> 6;
#pragma unroll
        for (int t = 0; t < 8; t++) {
            const int c = (cb + 4 * t) * 4;
            float4 va = *(const float4*)(A + (size_t)(m0 + r) * 128 + c);
            sm.As[c + 0][r] = va.x; sm.As[c + 1][r] = va.y;
            sm.As[c + 2][r] = va.z; sm.As[c + 3][r] = va.w;
            float4 vw = *(const float4*)(W + (size_t)(n0 + r) * 128 + c);
            sm.Ws[c + 0][r] = vw.x; sm.Ws[c + 1][r] = vw.y;
            sm.Ws[c + 2][r] = vw.z; sm.Ws[c + 3][r] = vw.w;
        }
    }
    __syncthreads();

    float acc[4][4];
#pragma unroll
    for (int i = 0; i < 4; i++)
#pragma unroll
        for (int j = 0; j < 4; j++) acc[i][j] = 0.f;

#pragma unroll 16
    for (int kk = 0; kk < 128; kk++) {
        const float4 a = *(const float4*)&sm.As[kk][ty * 4];
        const float4 b = *(const float4*)&sm.Ws[kk][tx * 4];
        acc[0][0] += a.x * b.x; acc[0][1] += a.x * b.y; acc[0][2] += a.x * b.z; acc[0][3] += a.x * b.w;
        acc[1][0] += a.y * b.x; acc[1][1] += a.y * b.y; acc[1][2] += a.y * b.z; acc[1][3] += a.y * b.w;
        acc[2][0] += a.z * b.x; acc[2][1] += a.z * b.y; acc[2][2] += a.z * b.z; acc[2][3] += a.z * b.w;
        acc[3][0] += a.w * b.x; acc[3][1] += a.w * b.y; acc[3][2] += a.w * b.z; acc[3][3] += a.w * b.w;
    }

#pragma unroll
    for (int i = 0; i < 4; i++) {
        const int m = m0 + ty * 4 + i;
#pragma unroll
        for (int j = 0; j < 4; j++) {
            const int n = n0 + tx * 4 + j;
            C[(size_t)m * N + n] = acc[i][j] + bias[n];
        }
    }
}

// ============================================================================
// polea_flat: pass1 policy = gelu(leaky(H2p0+H2p1+ab2) @ aw3^T + ab3)
//             pass2 ea = policy @ eaw_pol^T + ea_obs
// ============================================================================
__device__ __forceinline__ void polea_flat(
    PoleaF& sm, int bx, int by,
    const float* __restrict__ H2p, const float* __restrict__ ab2,
    const float* __restrict__ aw3, const float* __restrict__ ab3,
    const float* __restrict__ eaw, const float* __restrict__ eaobs,
    float* __restrict__ out_policy, float* __restrict__ eoea)
{
    const int tid = threadIdx.x;
    const int tx = tid & 15, ty = tid >> 4;
    const int m0 = by * 32, n0 = bx * 64;

    // fill A = leaky(H2p0 + H2p1 + ab2), row-major
#pragma unroll
    for (int t = 0; t < 4; t++) {
        const int f = tid + t * 256;
        const int r = f >> 5, c = (f & 31) * 4;
        const size_t off = (size_t)(m0 + r) * 128 + c;
        const float4 p0 = *(const float4*)(H2p + off);
        const float4 p1 = *(const float4*)(H2p + (size_t)LL * 128 + off);
        const float4 bb = *(const float4*)(ab2 + c);
        float4 v;
        v.x = p0.x + p1.x + bb.x; v.x = (v.x > 0.f) ? v.x : 0.01f * v.x;
        v.y = p0.y + p1.y + bb.y; v.y = (v.y > 0.f) ? v.y : 0.01f * v.y;
        v.z = p0.z + p1.z + bb.z; v.z = (v.z > 0.f) ? v.z : 0.01f * v.z;
        v.w = p0.w + p1.w + bb.w; v.w = (v.w > 0.f) ? v.w : 0.01f * v.w;
        *(float4*)&sm.Ar[r][c] = v;
    }
    // fill W = aw3 (rows < 32, else 0)
    {
        const int n = tid & 63;
        const int cb = tid >> 6;
#pragma unroll
        for (int t = 0; t < 8; t++) {
            const int c = (cb + 4 * t) * 4;
            float4 v = make_float4(0.f, 0.f, 0.f, 0.f);
            if (n < 32) v = *(const float4*)(aw3 + (size_t)n * 128 + c);
            sm.Ws[c + 0][n] = v.x; sm.Ws[c + 1][n] = v.y;
            sm.Ws[c + 2][n] = v.z; sm.Ws[c + 3][n] = v.w;
        }
    }
    __syncthreads();

    {
        float acc[2][4];
#pragma unroll
        for (int i = 0; i < 2; i++)
#pragma unroll
            for (int j = 0; j < 4; j++) acc[i][j] = 0.f;
        const float* a0p = &sm.Ar[ty * 2][0];
        const float* a1p = &sm.Ar[ty * 2 + 1][0];
#pragma unroll 32
        for (int kk = 0; kk < 128; kk++) {
            const float a0 = a0p[kk];
            const float a1 = a1p[kk];
            const float4 b = *(const float4*)&sm.Ws[kk][tx * 4];
            acc[0][0] += a0 * b.x; acc[0][1] += a0 * b.y;
            acc[0][2] += a0 * b.z; acc[0][3] += a0 * b.w;
            acc[1][0] += a1 * b.x; acc[1][1] += a1 * b.y;
            acc[1][2] += a1 * b.z; acc[1][3] += a1 * b.w;
        }
        __syncthreads();
        if (tx < 8) {
#pragma unroll
            for (int i = 0; i < 2; i++) {
                const int r = ty * 2 + i;
#pragma unroll
                for (int j = 0; j < 4; j++) {
                    const int n = tx * 4 + j;
                    float v = acc[i][j] + ab3[n];
                    v = 0.5f * v * (1.0f + erff(v * 0.70710678118654752f));
                    sm.Pol[r][n] = v;
                    if (bx == 0) out_policy[(size_t)(m0 + r) * 32 + n] = v;
                }
            }
        }
    }
    __syncthreads();

    // stage eaw pol-part: Wp[k][n] = eaw[(n0+n)*160 + 128 + k]
    for (int idx = tid; idx < 2048; idx += 256) {
        const int k = idx >> 6, n = idx & 63;
        sm.Wp[k][n] = eaw[(size_t)(n0 + n) * 160 + 128 + k];
    }
    __syncthreads();

    {
        float acc[2][4];
#pragma unroll
        for (int i = 0; i < 2; i++)
#pragma unroll
            for (int j = 0; j < 4; j++) acc[i][j] = 0.f;
#pragma unroll
        for (int kk = 0; kk < 32; kk++) {
            const float a0 = sm.Pol[ty * 2][kk];
            const float a1 = sm.Pol[ty * 2 + 1][kk];
            const float4 b = *(const float4*)&sm.Wp[kk][tx * 4];
            acc[0][0] += a0 * b.x; acc[0][1] += a0 * b.y;
            acc[0][2] += a0 * b.z; acc[0][3] += a0 * b.w;
            acc[1][0] += a1 * b.x; acc[1][1] += a1 * b.y;
            acc[1][2] += a1 * b.z; acc[1][3] += a1 * b.w;
        }
#pragma unroll
        for (int i = 0; i < 2; i++) {
            const int m = m0 + ty * 2 + i;
#pragma unroll
            for (int j = 0; j < 4; j++) {
                const int n = n0 + tx * 4 + j;
                eoea[(size_t)(768 + m) * 128 + n] =
                    acc[i][j] + eaobs[(size_t)m * 128 + n];
            }
        }
    }
}

// ============================================================================
// flash_body / cls_body: unchanged (R8-proven)
// ============================================================================
__device__ __forceinline__ void flash_body(
    char* raw, int q, int h, int l0,
    const float* __restrict__ qkvd,
    float* __restrict__ fO, float* __restrict__ fM, float* __restrict__ fL)
{
    FlashS& sm = *reinterpret_cast<FlashS*>(raw);
    const int tid = threadIdx.x;
    const float* Qb = qkvd + h * 32;
    const float* Kb = qkvd + 128 + h * 32;
    const float* Vb = qkvd + 256 + h * 32;

#pragma unroll
    for (int t = 0; t < 2; t++) {
        const int f = tid + t * 256;
        const int r = f >> 3, c = (f & 7) * 4;
        float4 v = *(const float4*)(Qb + (size_t)(l0 + r) * QKVW + c);
        sm.Qs[c + 0][r] = v.x; sm.Qs[c + 1][r] = v.y;
        sm.Qs[c + 2][r] = v.z; sm.Qs[c + 3][r] = v.w;
    }
    if (tid < 64) { sm.Ms[tid] = -1e30f; sm.Ls[tid] = 0.f; }

    float O[2][4];
#pragma unroll
    for (int i = 0; i < 2; i++)
#pragma unroll
        for (int j = 0; j < 4; j++) O[i][j] = 0.f;

    const int txA = tid & 15, tyA = tid >> 4;
    const int rB = tid >> 2,  hB = tid & 3;
    const int txC = tid & 7,  tyC = tid >> 3;

    const int mbeg = q * 256;
    for (int m0k = mbeg; m0k < mbeg + 256; m0k += 64) {
        __syncthreads();
#pragma unroll
        for (int t = 0; t < 2; t++) {
            const int f = tid + t * 256;
            const int r = f >> 3, c = (f & 7) * 4;
            float4 kv = *(const float4*)(Kb + (size_t)(m0k + r) * QKVW + c);
            sm.Ks[c + 0][r] = kv.x; sm.Ks[c + 1][r] = kv.y;
            sm.Ks[c + 2][r] = kv.z; sm.Ks[c + 3][r] = kv.w;
            float4 vv = *(const float4*)(Vb + (size_t)(m0k + r) * QKVW + c);
            *(float4*)&sm.Vs[r][c] = vv;
        }
        __syncthreads();

        float fa[4][4];
#pragma unroll
        for (int i = 0; i < 4; i++)
#pragma unroll
            for (int j = 0; j < 4; j++) fa[i][j] = 0.f;
#pragma unroll 8
        for (int d = 0; d < 32; d++) {
            float4 a = *(const float4*)&sm.Qs[d][tyA * 4];
            float4 b = *(const float4*)&sm.Ks[d][txA * 4];
            fa[0][0] += a.x * b.x; fa[0][1] += a.x * b.y; fa[0][2] += a.x * b.z; fa[0][3] += a.x * b.w;
            fa[1][0] += a.y * b.x; fa[1][1] += a.y * b.y; fa[1][2] += a.y * b.z; fa[1][3] += a.y * b.w;
            fa[2][0] += a.z * b.x; fa[2][1] += a.z * b.y; fa[2][2] += a.z * b.z; fa[2][3] += a.z * b.w;
            fa[3][0] += a.w * b.x; fa[3][1] += a.w * b.y; fa[3][2] += a.w * b.z; fa[3][3] += a.w * b.w;
        }
        const float sc = 0.17677669529663687f;
#pragma unroll
        for (int i = 0; i < 4; i++)
#pragma unroll
            for (int j = 0; j < 4; j++)
                sm.Ss[tyA * 4 + i][txA * 4 + j] = fa[i][j] * sc;
        __syncthreads();

        {
            const float* srow = &sm.Ss[rB][hB * 16];
            float mloc = -1e30f;
#pragma unroll
            for (int j = 0; j < 16; j++) mloc = fmaxf(mloc, srow[j]);
            mloc = fmaxf(mloc, __shfl_xor_sync(0xffffffffu, mloc, 1));
            mloc = fmaxf(mloc, __shfl_xor_sync(0xffffffffu, mloc, 2));
            float m_old = sm.Ms[rB];
            float m_new = fmaxf(m_old, mloc);
            float corr = __expf(m_old - m_new);
            float s = 0.f;
#pragma unroll
            for (int j = 0; j < 16; j++) {
                float e = __expf(srow[j] - m_new);
                sm.Pt[hB * 16 + j][rB] = e;
                s += e;
            }
            s += __shfl_xor_sync(0xffffffffu, s, 1);
            s += __shfl_xor_sync(0xffffffffu, s, 2);
            if (hB == 0) {
                sm.Ms[rB] = m_new;
                sm.Ls[rB] = sm.Ls[rB] * corr + s;
                sm.Cs[rB] = corr;
            }
        }
        __syncthreads();

        const float c0 = sm.Cs[tyC * 2];
        const float c1 = sm.Cs[tyC * 2 + 1];
#pragma unroll
        for (int j = 0; j < 4; j++) { O[0][j] *= c0; O[1][j] *= c1; }
#pragma unroll 8
        for (int mm = 0; mm < 64; mm++) {
            const float a0 = sm.Pt[mm][tyC * 2];
            const float a1 = sm.Pt[mm][tyC * 2 + 1];
            float4 b = *(const float4*)&sm.Vs[mm][txC * 4];
            O[0][0] += a0 * b.x; O[0][1] += a0 * b.y; O[0][2] += a0 * b.z; O[0][3] += a0 * b.w;
            O[1][0] += a1 * b.x; O[1][1] += a1 * b.y; O[1][2] += a1 * b.z; O[1][3] += a1 * b.w;
        }
    }

    const int pb = q * 4 + h;
#pragma unroll
    for (int i = 0; i < 2; i++) {
        const int r = tyC * 2 + i;
        const int l = l0 + r;
        *(float4*)(fO + ((size_t)pb * LL + l) * 32 + txC * 4) = *(float4*)&O[i][0];
        if (txC == 0) {
            fM[(size_t)pb * LL + l] = sm.Ms[r];
            fL[(size_t)pb * LL + l] = sm.Ls[r];
        }
    }
}

__device__ __forceinline__ void cls_body(
    char* raw, int k, int h,
    const float* __restrict__ qkvd, float* __restrict__ aod)
{
    ClsS& sm = *reinterpret_cast<ClsS*>(raw);
    const int tid = threadIdx.x;

#pragma unroll
    for (int t = 0; t < 3; t++) {
        const int f = tid + t * 256;
        const int r = f >> 3, c = (f & 7) * 4;
        const int b = r >> 1, cc = r & 1;
        const int j = cc ? (k - 1) : k;
        const float* base = qkvd + (size_t)(768 + b * 16 + j) * QKVW + h * 32 + c;
        *(float4*)&sm.Qc[r][c] = *(const float4*)(base);
        *(float4*)&sm.Kc[r][c] = *(const float4*)(base + 128);
        *(float4*)&sm.Vc[r][c] = *(const float4*)(base + 256);
    }
    __syncthreads();

    const int tx = tid & 15, ty = tid >> 4;
    {
        float acc[6][6];
#pragma unroll
        for (int i = 0; i < 6; i++)
#pragma unroll
            for (int j = 0; j < 6; j++) acc[i][j] = 0.f;
#pragma unroll 8
        for (int d = 0; d < 32; d++) {
            float a[6], b[6];
#pragma unroll
            for (int i = 0; i < 6; i++) a[i] = sm.Qc[ty * 6 + i][d];
#pragma unroll
            for (int j = 0; j < 6; j++) b[j] = sm.Kc[tx * 6 + j][d];
#pragma unroll
            for (int i = 0; i < 6; i++)
#pragma unroll
                for (int j = 0; j < 6; j++) acc[i][j] += a[i] * b[j];
        }
        const float scl = 0.17677669529663687f;
#pragma unroll
        for (int i = 0; i < 6; i++)
#pragma unroll
            for (int j = 0; j < 6; j++)
                sm.Sc[ty * 6 + i][tx * 6 + j] = acc[i][j] * scl;
    }
    __syncthreads();

    if (tid < 96) {
        float mx = -1e30f;
#pragma unroll 8
        for (int m = 0; m < 96; m++) mx = fmaxf(mx, sm.Sc[tid][m]);
        const float w0 = (float)k, w1 = (float)(16 - k);
        float s = 0.f;
#pragma unroll 8
        for (int m = 0; m < 96; m++) {
            float w = (m & 1) ? w1 : w0;
            float e = w * __expf(sm.Sc[tid][m] - mx);
            sm.Sc[tid][m] = e;
            s += e;
        }
        const float inv = 1.0f / s;
#pragma unroll 8
        for (int m = 0; m < 96; m++) sm.Sc[tid][m] *= inv;
    }
    __syncthreads();

    const int txo = tid & 7, tyo = tid >> 3;
    float o[3][4];
#pragma unroll
    for (int i = 0; i < 3; i++)
#pragma unroll
        for (int j = 0; j < 4; j++) o[i][j] = 0.f;
#pragma unroll 8
    for (int m = 0; m < 96; m++) {
        float a[3];
#pragma unroll
        for (int i = 0; i < 3; i++) a[i] = sm.Sc[tyo * 3 + i][m];
        float4 b = *(const float4*)&sm.Vc[m][txo * 4];
#pragma unroll
        for (int i = 0; i < 3; i++) {
            o[i][0] += a[i] * b.x; o[i][1] += a[i] * b.y;
            o[i][2] += a[i] * b.z; o[i][3] += a[i] * b.w;
        }
    }
#pragma unroll
    for (int i = 0; i < 3; i++) {
        const int row = 768 + (k - 1) * 96 + tyo * 3 + i;
        *(float4*)(aod + (size_t)row * 128 + h * 32 + txo * 4) = *(float4*)&o[i][0];
    }
}

// ============================================================================
// dispatch kernels
// ============================================================================
__global__ void __launch_bounds__(256)
k_L1(const float* obs, const float* aw1, const float* ab1,
     const float* eow, const float* eob,
     float* H1, float* out_eo, float* eoea)
{
    extern __shared__ char raw[];
    g32_flat<ACT_NONE, true, false, false, false>(
        *(G32F*)raw, blockIdx.x % 6, blockIdx.x / 6,
        obs, 128, aw1, eow, 128, ab1, eob, nullptr,
        nullptr, nullptr, nullptr, nullptr, nullptr,
        H1, out_eo, eoea, 0, 384);
}

__global__ void __launch_bounds__(256)
k_L2(const float* H1, const float* aw2, float* H2p,
     const float* obs, const float* eaw, const float* eab, float* eaobs)
{
    extern __shared__ char raw[];
    G32F& sm = *(G32F*)raw;
    const int b = blockIdx.x;
    if (b < 96) {
        const int kz = b / 48, r = b % 48;
        g32_flat<ACT_NONE, false, false, false, false>(
            sm, r % 2, r / 2,
            H1 + kz * 128, 256, aw2 + kz * 128, nullptr, 256,
            nullptr, nullptr, nullptr, nullptr, nullptr, nullptr, nullptr, nullptr,
            H2p + (size_t)kz * LL * 128, nullptr, nullptr, 0, 128);
    } else {
        const int r = b - 96;
        g32_flat<ACT_NONE, false, false, false, false>(
            sm, r % 2, r / 2,
            obs, 128, eaw, nullptr, 160,
            eab, nullptr, nullptr, nullptr, nullptr, nullptr, nullptr, nullptr,
            eaobs, nullptr, nullptr, 0, 128);
    }
}

__global__ void __launch_bounds__(256)
k_L3(const float* H2p, const float* ab2, const float* aw3, const float* ab3,
     const float* eaw, const float* eaobs, float* out_policy, float* eoea,
     const float* riw, const float* rib, float* x1d)
{
    extern __shared__ char raw[];
    const int b = blockIdx.x;
    if (b < 48) {
        polea_flat(*(PoleaF*)raw, b % 2, b / 2,
                   H2p, ab2, aw3, ab3, eaw, eaobs, out_policy, eoea);
    } else {
        const int r = b - 48;
        g32_flat<ACT_RELU, false, false, false, false>(
            *(G32F*)raw, r % 2, r / 2,
            eoea, 128, riw, nullptr, 128,
            rib, nullptr, nullptr, nullptr, nullptr, nullptr, nullptr, nullptr,
            x1d, nullptr, nullptr, 0, 128);
    }
}

__global__ void __launch_bounds__(256)
k_L4(const float* eoea, const float* riw, const float* rib, float* x1d,
     const float* miw, const float* mib, float* qkvd)
{
    extern __shared__ char raw[];
    const int b = blockIdx.x;
    if (b < 48) {
        g32_flat<ACT_RELU, false, false, false, false>(
            *(G32F*)raw, b % 2, b / 2,
            eoea + 768 * 128, 128, riw, nullptr, 128,
            rib, nullptr, nullptr, nullptr, nullptr, nullptr, nullptr, nullptr,
            x1d + 768 * 128, nullptr, nullptr, 768, 128);
    } else {
        const int r = b - 48;
        g64_flat(*(G64F*)raw, r % 6, r / 6, x1d, miw, mib, qkvd, 384);
    }
}

__global__ void __launch_bounds__(256)
k_L5(const float* qkvd, float* fO, float* fM, float* fL,
     const float* x1d, const float* miw, const float* mib, float* qkvd_a)
{
    extern __shared__ char raw[];
    const int b = blockIdx.x;
    if (b < 144) {
        const int q = b / 48, rem = b % 48;
        flash_body(raw, q, rem / 12, (rem % 12) * 64, qkvd, fO, fM, fL);
    } else {
        const int r = b - 144;
        g64_flat(*(G64F*)raw, r % 6, r / 6,
                 x1d + 768 * 128, miw, mib, qkvd_a + 768 * QKVW, 384);
    }
}

__global__ void __launch_bounds__(256)
k_L6(const float* qkvd, float* aod,
     const float* fO, const float* fM, const float* fL,
     const float* x1d, const float* mow, const float* mob, float* aopd)
{
    extern __shared__ char raw[];
    const int b = blockIdx.x;
    if (b < 60) {
        cls_body(raw, b % 15 + 1, b / 15, qkvd, aod);
    } else {
        const int r = b - 60;
        g32_flat<ACT_NONE, false, true, true, false>(
            *(G32F*)raw, r % 2, r / 2,
            nullptr, 128, mow, nullptr, 128,
            mob, nullptr, x1d, fO, fM, fL, nullptr, nullptr,
            aopd, nullptr, nullptr, 0, 128);
    }
}

__global__ void __launch_bounds__(256)
k_L7(const float* aod, const float* x1d, const float* mow, const float* mob,
     float* aopd, const float* roww, const float* rob,
     const float* qw, float* qvp)
{
    extern __shared__ char raw[];
    const int b = blockIdx.x;
    if (b < 92) {
        g32_flat<ACT_NONE, false, true, false, false>(
            *(G32F*)raw, b % 2, b / 2,
            aod + 768 * 128, 128, mow, nullptr, 128,
            mob, nullptr, x1d, nullptr, nullptr, nullptr, nullptr, nullptr,
            aopd + 768 * 128, nullptr, nullptr, 768, 128);
    } else {
        const int r = b - 92;
        g32_flat<ACT_RELU, false, false, false, true>(
            *(G32F*)raw, r % 2, r / 2,
            aopd, 128, roww, nullptr, 128,
            rob, nullptr, nullptr, nullptr, nullptr, nullptr, qw, qvp,
            nullptr, nullptr, nullptr, 0, 128);
    }
}

// L8 = G8 a-rows + (last block) q_values assembly
__global__ void __launch_bounds__(256)
k_L8(const float* aopd, const float* roww, const float* rob,
     const float* qw, float* qvp, const float* qb, float* out_q)
{
    extern __shared__ char raw[];
    g32_flat<ACT_RELU, false, false, false, true>(
        *(G32F*)raw, blockIdx.x % 2, blockIdx.x / 2,
        aopd + 768 * 128, 128, roww, nullptr, 128,
        rob, nullptr, nullptr, nullptr, nullptr, nullptr, qw, qvp,
        nullptr, nullptr, nullptr, 768, 128);

    // last-block assembly (deterministic; counter self-resets for graph replay)
    __shared__ int is_last;
    __threadfence();
    __syncthreads();
    if (threadIdx.x == 0) is_last = (atomicAdd(&g_ctr, 1) == gridDim.x - 1);
    __syncthreads();
    if (is_last) {
        if (threadIdx.x == 0) g_ctr = 0;
        __threadfence();
        const float qb0 = qb[0];
        for (int l = threadIdx.x; l < 768; l += 256) {
            const int b = l >> 4, i = l & 15;
            float s = qvp[l] + qvp[MPOST + l] + qb0;
#pragma unroll
            for (int k = 1; k < 16; k++) {
                const int c = (i < k) ? 0 : 1;
                const int row = 768 + (k - 1) * 96 + b * 2 + c;
                s += qvp[row] + qvp[MPOST + row] + qb0;
            }
            out_q[l] = s;
        }
    }
}

extern "C" void kernel_launch(void* const* d_in, const int* in_sizes, int n_in,
                              void* d_out, int out_size)
{
    const float* obs = (const float*)d_in[0];
    const float* aw1 = (const float*)d_in[1];  const float* ab1 = (const float*)d_in[2];
    const float* aw2 = (const float*)d_in[3];  const float* ab2 = (const float*)d_in[4];
    const float* aw3 = (const float*)d_in[5];  const float* ab3 = (const float*)d_in[6];
    const float* eow = (const float*)d_in[7];  const float* eob = (const float*)d_in[8];
    const float* eaw = (const float*)d_in[9];  const float* eab = (const float*)d_in[10];
    const float* riw = (const float*)d_in[11]; const float* rib = (const float*)d_in[12];
    const float* roww = (const float*)d_in[13]; const float* rob = (const float*)d_in[14];
    const float* miw = (const float*)d_in[15]; const float* mib = (const float*)d_in[16];
    const float* mow = (const float*)d_in[17]; const float* mob = (const float*)d_in[18];
    const float* qw  = (const float*)d_in[19]; const float* qb  = (const float*)d_in[20];

    float* out = (float*)d_out;
    float* out_policy = out + OUT_POLICY;
    float* out_q      = out + OUT_Q;
    float* out_eo     = out + OUT_EO;

    float *H1, *H2p, *eaobs, *eoea, *x1d, *qkvd, *aod, *aopd, *qvp, *fO, *fM, *fL;
    cudaGetSymbolAddress((void**)&H1, g_H1);
    cudaGetSymbolAddress((void**)&H2p, g_H2p);
    cudaGetSymbolAddress((void**)&eaobs, g_eaobs);
    cudaGetSymbolAddress((void**)&eoea, g_eoea);
    cudaGetSymbolAddress((void**)&x1d, g_x1d);
    cudaGetSymbolAddress((void**)&qkvd, g_qkvd);
    cudaGetSymbolAddress((void**)&aod, g_aod);
    cudaGetSymbolAddress((void**)&aopd, g_aopd);
    cudaGetSymbolAddress((void**)&qvp, g_qvp);
    cudaGetSymbolAddress((void**)&fO, g_fO);
    cudaGetSymbolAddress((void**)&fM, g_fM);
    cudaGetSymbolAddress((void**)&fL, g_fL);

    const int sG32  = (int)sizeof(G32F);
    const int sL3   = (int)(sizeof(PoleaF) > sizeof(G32F) ? sizeof(PoleaF) : sizeof(G32F));
    const int sL45  = (int)(sizeof(G64F) > sizeof(FlashS) ? sizeof(G64F) : sizeof(FlashS));
    const int sL6   = (int)(sizeof(ClsS) > sizeof(G32F) ? sizeof(ClsS) : sizeof(G32F));

    cudaFuncSetAttribute(k_L1, cudaFuncAttributeMaxDynamicSharedMemorySize, sG32);
    cudaFuncSetAttribute(k_L2, cudaFuncAttributeMaxDynamicSharedMemorySize, sG32);
    cudaFuncSetAttribute(k_L3, cudaFuncAttributeMaxDynamicSharedMemorySize, sL3);
    cudaFuncSetAttribute(k_L4, cudaFuncAttributeMaxDynamicSharedMemorySize, sL45);
    cudaFuncSetAttribute(k_L5, cudaFuncAttributeMaxDynamicSharedMemorySize, sL45);
    cudaFuncSetAttribute(k_L6, cudaFuncAttributeMaxDynamicSharedMemorySize, sL6);
    cudaFuncSetAttribute(k_L7, cudaFuncAttributeMaxDynamicSharedMemorySize, sG32);
    cudaFuncSetAttribute(k_L8, cudaFuncAttributeMaxDynamicSharedMemorySize, sG32);

    dim3 blk(256);

    k_L1<<<144, blk, sG32>>>(obs, aw1, ab1, eow, eob, H1, out_eo, eoea);
    k_L2<<<144, blk, sG32>>>(H1, aw2, H2p, obs, eaw, eab, eaobs);
    k_L3<<<96,  blk, sL3 >>>(H2p, ab2, aw3, ab3, eaw, eaobs, out_policy, eoea,
                             riw, rib, x1d);
    k_L4<<<120, blk, sL45>>>(eoea, riw, rib, x1d, miw, mib, qkvd);
    k_L5<<<216, blk, sL45>>>(qkvd, fO, fM, fL, x1d, miw, mib, qkvd);
    k_L6<<<108, blk, sL6 >>>(qkvd, aod, fO, fM, fL, x1d, mow, mob, aopd);
    k_L7<<<140, blk, sG32>>>(aod, x1d, mow, mob, aopd, roww, rob, qw, qvp);
    k_L8<<<92,  blk, sG32>>>(aopd, roww, rob, qw, qvp, qb, out_q);

    (void)in_sizes; (void)n_in; (void)out_size;
}